// round 7
// baseline (speedup 1.0000x reference)
#include <cuda_runtime.h>
#include <math.h>

// Problem constants
#define B_DIM 8
#define S_DIM 2048
#define D_MODEL 512
#define D_K 64
#define EPSV 1e-6f
#define ROWS_PER_BLK 16   // q rows per attention block

// Scratch for projected q (pre-scaled by dk^-0.5), k, v: each 8*2048*64 f32 = 4MB
__device__ float g_q[B_DIM * S_DIM * D_K];
__device__ float g_k[B_DIM * S_DIM * D_K];
__device__ float g_v[B_DIM * S_DIM * D_K];

// ---------------------------------------------------------------------------
// Projection: Out[r][d] = (sum_m X[r][m] * W[d][m] + bias[d]) * scale
// X: (16384, 512) row-major, W: (64, 512) row-major (both K-major -> dot along
// contiguous). Tile: 64 rows x 64 cols per block, 256 threads, 4x4 micro-tile.
// blockIdx.y selects which of {q,k,v}.
// ---------------------------------------------------------------------------
__global__ __launch_bounds__(256) void proj_kernel(
    const float* __restrict__ Xq, const float* __restrict__ Xk, const float* __restrict__ Xv,
    const float* __restrict__ Wq, const float* __restrict__ bq,
    const float* __restrict__ Wk, const float* __restrict__ bk,
    const float* __restrict__ Wv, const float* __restrict__ bv)
{
    const float* X; const float* W; const float* bias; float* Out; float scale;
    if (blockIdx.y == 0)      { X = Xq; W = Wq; bias = bq; Out = g_q; scale = 0.125f; } // 64^-0.5
    else if (blockIdx.y == 1) { X = Xk; W = Wk; bias = bk; Out = g_k; scale = 1.0f; }
    else                      { X = Xv; W = Wv; bias = bv; Out = g_v; scale = 1.0f; }

    __shared__ float Xs[64 * 17];   // pad 17 to break conflicts
    __shared__ float Ws[64 * 17];

    const int t  = threadIdx.x;
    const int tx = t & 15;          // col group 0..15
    const int ty = t >> 4;          // row group 0..15
    const int rowBase = blockIdx.x * 64;

    const int lrow = t >> 2;        // 0..63 : row loaded by this thread
    const int lk   = (t & 3) * 4;   // 0,4,8,12 : k-offset within 16-chunk

    float acc[4][4];
#pragma unroll
    for (int u = 0; u < 4; u++)
#pragma unroll
        for (int v = 0; v < 4; v++) acc[u][v] = 0.0f;

    for (int k0 = 0; k0 < D_MODEL; k0 += 16) {
        float4 xv = *(const float4*)(X + (size_t)(rowBase + lrow) * D_MODEL + k0 + lk);
        float4 wv = *(const float4*)(W + (size_t)lrow * D_MODEL + k0 + lk);
        __syncthreads();   // protect previous iteration's smem reads
        Xs[lrow * 17 + lk + 0] = xv.x; Xs[lrow * 17 + lk + 1] = xv.y;
        Xs[lrow * 17 + lk + 2] = xv.z; Xs[lrow * 17 + lk + 3] = xv.w;
        Ws[lrow * 17 + lk + 0] = wv.x; Ws[lrow * 17 + lk + 1] = wv.y;
        Ws[lrow * 17 + lk + 2] = wv.z; Ws[lrow * 17 + lk + 3] = wv.w;
        __syncthreads();
#pragma unroll
        for (int kk = 0; kk < 16; kk++) {
            float a0 = Xs[(ty * 4 + 0) * 17 + kk];
            float a1 = Xs[(ty * 4 + 1) * 17 + kk];
            float a2 = Xs[(ty * 4 + 2) * 17 + kk];
            float a3 = Xs[(ty * 4 + 3) * 17 + kk];
            float b0 = Ws[(tx * 4 + 0) * 17 + kk];
            float b1 = Ws[(tx * 4 + 1) * 17 + kk];
            float b2 = Ws[(tx * 4 + 2) * 17 + kk];
            float b3 = Ws[(tx * 4 + 3) * 17 + kk];
            acc[0][0] = fmaf(a0, b0, acc[0][0]); acc[0][1] = fmaf(a0, b1, acc[0][1]);
            acc[0][2] = fmaf(a0, b2, acc[0][2]); acc[0][3] = fmaf(a0, b3, acc[0][3]);
            acc[1][0] = fmaf(a1, b0, acc[1][0]); acc[1][1] = fmaf(a1, b1, acc[1][1]);
            acc[1][2] = fmaf(a1, b2, acc[1][2]); acc[1][3] = fmaf(a1, b3, acc[1][3]);
            acc[2][0] = fmaf(a2, b0, acc[2][0]); acc[2][1] = fmaf(a2, b1, acc[2][1]);
            acc[2][2] = fmaf(a2, b2, acc[2][2]); acc[2][3] = fmaf(a2, b3, acc[2][3]);
            acc[3][0] = fmaf(a3, b0, acc[3][0]); acc[3][1] = fmaf(a3, b1, acc[3][1]);
            acc[3][2] = fmaf(a3, b2, acc[3][2]); acc[3][3] = fmaf(a3, b3, acc[3][3]);
        }
    }

#pragma unroll
    for (int u = 0; u < 4; u++) {
        int r = rowBase + ty * 4 + u;
#pragma unroll
        for (int v = 0; v < 4; v++) {
            int c = tx * 4 + v;
            Out[(size_t)r * D_K + c] = (acc[u][v] + bias[c]) * scale;
        }
    }
}

// ---------------------------------------------------------------------------
// Attention: per block = (batch b, 16 q rows). Scores (16 x 2048 f32 = 128KB)
// live in dynamic smem. Phases: QK -> mask -> softmax (+weight write) -> PV.
// ---------------------------------------------------------------------------
__global__ __launch_bounds__(256) void attn_kernel(
    const int* __restrict__ amask,
    float* __restrict__ out_attn,   // (B,S,64)
    float* __restrict__ out_w)      // (B,S,S)
{
    extern __shared__ float sh[];
    float* sc = sh;                               // [16][2048]
    float* qs = sh + ROWS_PER_BLK * S_DIM;        // [16][64]

    const int b  = blockIdx.y;
    const int q0 = blockIdx.x * ROWS_PER_BLK;
    const int tid = threadIdx.x;

    // Load q tile (already scaled): 16*64 = 1024 floats, one float4/thread
    {
        const float4* qsrc = (const float4*)(g_q + ((size_t)b * S_DIM + q0) * D_K);
        ((float4*)qs)[tid] = qsrc[tid];
    }
    __syncthreads();

    const float* kb = g_k + (size_t)b * S_DIM * D_K;
    const int*   mb = amask + ((size_t)b * S_DIM + q0) * S_DIM;

    // ---- Phase 1: scores s[i][j] = qhat_i . k_j, then EPS masking ----
    for (int j = tid; j < S_DIM; j += 256) {
        const float4* kr = (const float4*)(kb + (size_t)j * D_K);
        float acc[ROWS_PER_BLK];
#pragma unroll
        for (int i = 0; i < ROWS_PER_BLK; i++) acc[i] = 0.0f;

#pragma unroll 4
        for (int mc = 0; mc < 16; mc++) {        // 16 float4 chunks of dim 64
            float4 kv = kr[mc];
#pragma unroll
            for (int i = 0; i < ROWS_PER_BLK; i++) {
                float4 qv = *(const float4*)(qs + i * D_K + mc * 4);  // broadcast LDS.128
                acc[i] = fmaf(qv.x, kv.x,
                         fmaf(qv.y, kv.y,
                         fmaf(qv.z, kv.z,
                         fmaf(qv.w, kv.w, acc[i]))));
            }
        }
#pragma unroll
        for (int i = 0; i < ROWS_PER_BLK; i++) {
            float s = acc[i];
            if (s == 0.0f) s = EPSV;                       // masked_fill(qk == 0, eps)
            if (mb[(size_t)i * S_DIM + j] == 0) s = EPSV;  // masked_fill(mask == 0, eps)
            sc[i * S_DIM + j] = s;
        }
    }
    __syncthreads();

    // ---- Phase 2: softmax per row; write normalized weights to gmem ----
    const int lane = tid & 31;
    const int warp = tid >> 5;
    for (int i = warp; i < ROWS_PER_BLK; i += 8) {
        float* row = sc + i * S_DIM;
        float mx = -3.402823466e38f;
        for (int j = lane; j < S_DIM; j += 32) mx = fmaxf(mx, row[j]);
#pragma unroll
        for (int o = 16; o; o >>= 1) mx = fmaxf(mx, __shfl_xor_sync(0xffffffffu, mx, o));
        float sum = 0.0f;
        for (int j = lane; j < S_DIM; j += 32) {
            float p = __expf(row[j] - mx);
            row[j] = p;
            sum += p;
        }
#pragma unroll
        for (int o = 16; o; o >>= 1) sum += __shfl_xor_sync(0xffffffffu, sum, o);
        float inv = 1.0f / sum;
        float* wr = out_w + ((size_t)b * S_DIM + q0 + i) * S_DIM;
        for (int j = lane; j < S_DIM; j += 32) {
            float p = row[j] * inv;
            row[j] = p;          // keep normalized prob in smem for PV
            wr[j]  = p;          // coalesced weight write
        }
    }
    __syncthreads();

    // ---- Phase 3: PV. Thread owns 2 rows x 2 head-dims (float2 V loads). ----
    const float* vb = g_v + (size_t)b * S_DIM * D_K;
    const int dp = tid & 31;    // float2 column pair (d = 2*dp, 2*dp+1)
    const int rp = tid >> 5;    // row pair (rows 2*rp, 2*rp+1)
    const float* r0 = sc + (2 * rp + 0) * S_DIM;
    const float* r1 = sc + (2 * rp + 1) * S_DIM;
    float a00 = 0.f, a01 = 0.f, a10 = 0.f, a11 = 0.f;
#pragma unroll 8
    for (int j = 0; j < S_DIM; j++) {
        float2 vv = ((const float2*)(vb + (size_t)j * D_K))[dp];  // coalesced, L1/L2 hot
        float p0 = r0[j];   // broadcast LDS
        float p1 = r1[j];
        a00 = fmaf(p0, vv.x, a00); a01 = fmaf(p0, vv.y, a01);
        a10 = fmaf(p1, vv.x, a10); a11 = fmaf(p1, vv.y, a11);
    }
    float* ob = out_attn + ((size_t)b * S_DIM + q0) * D_K;
    ((float2*)(ob + (2 * rp + 0) * D_K))[dp] = make_float2(a00, a01);
    ((float2*)(ob + (2 * rp + 1) * D_K))[dp] = make_float2(a10, a11);
}

// ---------------------------------------------------------------------------
extern "C" void kernel_launch(void* const* d_in, const int* in_sizes, int n_in,
                              void* d_out, int out_size)
{
    const float* query = (const float*)d_in[0];
    const float* key   = (const float*)d_in[1];
    const float* value = (const float*)d_in[2];
    const int*   amask = (const int*)d_in[3];
    const float* Wq = (const float*)d_in[4];
    const float* bq = (const float*)d_in[5];
    const float* Wk = (const float*)d_in[6];
    const float* bk = (const float*)d_in[7];
    const float* Wv = (const float*)d_in[8];
    const float* bv = (const float*)d_in[9];

    float* out_attn = (float*)d_out;                                     // (B,S,64)
    float* out_w    = (float*)d_out + (size_t)B_DIM * S_DIM * D_K;       // (B,S,S)

    // Projections: grid.x over 16384/64 row tiles, grid.y = {q,k,v}
    proj_kernel<<<dim3((B_DIM * S_DIM) / 64, 3), 256>>>(
        query, key, value, Wq, bq, Wk, bk, Wv, bv);

    // Fused attention
    const size_t smem = (size_t)(ROWS_PER_BLK * S_DIM + ROWS_PER_BLK * D_K) * sizeof(float); // 135168 B
    cudaFuncSetAttribute(attn_kernel, cudaFuncAttributeMaxDynamicSharedMemorySize, (int)smem);
    attn_kernel<<<dim3(S_DIM / ROWS_PER_BLK, B_DIM), 256, smem>>>(amask, out_attn, out_w);
}

// round 9
// speedup vs baseline: 1.8826x; 1.8826x over previous
#include <cuda_runtime.h>
#include <math.h>

#define B_DIM 8
#define S_DIM 2048
#define D_MODEL 512
#define D_K 64
#define EPSV 1e-6f

// Scratch for projected q (pre-scaled by dk^-0.5), k, v
__device__ float g_q[B_DIM * S_DIM * D_K];
__device__ float g_k[B_DIM * S_DIM * D_K];
__device__ float g_v[B_DIM * S_DIM * D_K];

// ---------------------------------------------------------------------------
// Projection (unchanged from R4): Out[r][d] = (X[r]·W[d] + bias[d]) * scale
// ---------------------------------------------------------------------------
__global__ __launch_bounds__(256) void proj_kernel(
    const float* __restrict__ Xq, const float* __restrict__ Xk, const float* __restrict__ Xv,
    const float* __restrict__ Wq, const float* __restrict__ bq,
    const float* __restrict__ Wk, const float* __restrict__ bk,
    const float* __restrict__ Wv, const float* __restrict__ bv)
{
    const float* X; const float* W; const float* bias; float* Out; float scale;
    if (blockIdx.y == 0)      { X = Xq; W = Wq; bias = bq; Out = g_q; scale = 0.125f; }
    else if (blockIdx.y == 1) { X = Xk; W = Wk; bias = bk; Out = g_k; scale = 1.0f; }
    else                      { X = Xv; W = Wv; bias = bv; Out = g_v; scale = 1.0f; }

    __shared__ float Xs[64 * 17];
    __shared__ float Ws[64 * 17];

    const int t  = threadIdx.x;
    const int tx = t & 15;
    const int ty = t >> 4;
    const int rowBase = blockIdx.x * 64;
    const int lrow = t >> 2;
    const int lk   = (t & 3) * 4;

    float acc[4][4];
#pragma unroll
    for (int u = 0; u < 4; u++)
#pragma unroll
        for (int v = 0; v < 4; v++) acc[u][v] = 0.0f;

    for (int k0 = 0; k0 < D_MODEL; k0 += 16) {
        float4 xv = *(const float4*)(X + (size_t)(rowBase + lrow) * D_MODEL + k0 + lk);
        float4 wv = *(const float4*)(W + (size_t)lrow * D_MODEL + k0 + lk);
        __syncthreads();
        Xs[lrow * 17 + lk + 0] = xv.x; Xs[lrow * 17 + lk + 1] = xv.y;
        Xs[lrow * 17 + lk + 2] = xv.z; Xs[lrow * 17 + lk + 3] = xv.w;
        Ws[lrow * 17 + lk + 0] = wv.x; Ws[lrow * 17 + lk + 1] = wv.y;
        Ws[lrow * 17 + lk + 2] = wv.z; Ws[lrow * 17 + lk + 3] = wv.w;
        __syncthreads();
#pragma unroll
        for (int kk = 0; kk < 16; kk++) {
            float a0 = Xs[(ty * 4 + 0) * 17 + kk];
            float a1 = Xs[(ty * 4 + 1) * 17 + kk];
            float a2 = Xs[(ty * 4 + 2) * 17 + kk];
            float a3 = Xs[(ty * 4 + 3) * 17 + kk];
            float b0 = Ws[(tx * 4 + 0) * 17 + kk];
            float b1 = Ws[(tx * 4 + 1) * 17 + kk];
            float b2 = Ws[(tx * 4 + 2) * 17 + kk];
            float b3 = Ws[(tx * 4 + 3) * 17 + kk];
            acc[0][0] = fmaf(a0, b0, acc[0][0]); acc[0][1] = fmaf(a0, b1, acc[0][1]);
            acc[0][2] = fmaf(a0, b2, acc[0][2]); acc[0][3] = fmaf(a0, b3, acc[0][3]);
            acc[1][0] = fmaf(a1, b0, acc[1][0]); acc[1][1] = fmaf(a1, b1, acc[1][1]);
            acc[1][2] = fmaf(a1, b2, acc[1][2]); acc[1][3] = fmaf(a1, b3, acc[1][3]);
            acc[2][0] = fmaf(a2, b0, acc[2][0]); acc[2][1] = fmaf(a2, b1, acc[2][1]);
            acc[2][2] = fmaf(a2, b2, acc[2][2]); acc[2][3] = fmaf(a2, b3, acc[2][3]);
            acc[3][0] = fmaf(a3, b0, acc[3][0]); acc[3][1] = fmaf(a3, b1, acc[3][1]);
            acc[3][2] = fmaf(a3, b2, acc[3][2]); acc[3][3] = fmaf(a3, b3, acc[3][3]);
        }
    }

#pragma unroll
    for (int u = 0; u < 4; u++) {
        int r = rowBase + ty * 4 + u;
#pragma unroll
        for (int v = 0; v < 4; v++) {
            int c = tx * 4 + v;
            Out[(size_t)r * D_K + c] = (acc[u][v] + bias[c]) * scale;
        }
    }
}

// ---------------------------------------------------------------------------
// QK^T + mask + softmax. Block = (batch, 16 q rows) x all 2048 cols.
// 512 threads, thread tile 8 rows x 8 cols (acc[8][8]).
// K staged transposed in double-buffered smem (CH=4 k-slices x 2048 cols).
// Scores -> smem -> per-row softmax (16 warps) -> normalized weights to gmem.
// smem floats: sc [16][2048] = 32768 (first 16384 alias the two kt buffers),
//              qt [64][16]   at +32768.  Total 33792 floats = 135168 B.
// ---------------------------------------------------------------------------
#define QK_THREADS 512
#define CH 4

__global__ __launch_bounds__(QK_THREADS, 1) void qk_softmax_kernel(
    const int* __restrict__ amask, float* __restrict__ out_w)
{
    extern __shared__ float sh[];
    float* kt = sh;             // [2][CH][2048]
    float* sc = sh;             // [16][2048]
    float* qt = sh + 32768;     // [64][16] transposed q tile

    const int b   = blockIdx.y;
    const int q0  = blockIdx.x * 16;
    const int tid = threadIdx.x;
    const int tx  = tid & 255;   // col group: cols tx*8..+7
    const int ty  = tid >> 8;    // row group: rows ty*8..+7

    // Load q tile transposed: qt[kk][r] = q[q0+r][kk] (pre-scaled)
    {
        int r   = tid & 15;
        int kks = (tid >> 4) * 2;
        const float* qsrc = g_q + ((size_t)b * S_DIM + q0 + r) * D_K + kks;
        qt[(kks + 0) * 16 + r] = qsrc[0];
        qt[(kks + 1) * 16 + r] = qsrc[1];
    }

    const float* kb = g_k + (size_t)b * S_DIM * D_K;

    float acc[8][8];
#pragma unroll
    for (int u = 0; u < 8; u++)
#pragma unroll
        for (int v = 0; v < 8; v++) acc[u][v] = 0.0f;

    // Prologue: load + store chunk 0 (kk = 0..3) transposed: kt[0][cc][j] = K[j][cc]
    float4 pf[4];
#pragma unroll
    for (int i = 0; i < 4; i++) {
        int j = tid + 512 * i;
        pf[i] = *(const float4*)(kb + (size_t)j * D_K + 0);
    }
#pragma unroll
    for (int i = 0; i < 4; i++) {
        int j = tid + 512 * i;
        kt[0 * 2048 + j] = pf[i].x;
        kt[1 * 2048 + j] = pf[i].y;
        kt[2 * 2048 + j] = pf[i].z;
        kt[3 * 2048 + j] = pf[i].w;
    }
    __syncthreads();

    const int NCHUNK = D_K / CH;   // 16
    for (int c = 0; c < NCHUNK; c++) {
        const int buf = c & 1;
        // Prefetch next chunk (long-latency LDGs issued before compute)
        if (c + 1 < NCHUNK) {
            int kk0 = (c + 1) * CH;
#pragma unroll
            for (int i = 0; i < 4; i++) {
                int j = tid + 512 * i;
                pf[i] = *(const float4*)(kb + (size_t)j * D_K + kk0);
            }
        }
        // Compute CH k-steps from current buffer
#pragma unroll
        for (int s = 0; s < CH; s++) {
            int kk = c * CH + s;
            float4 a0 = *(const float4*)(qt + kk * 16 + ty * 8);
            float4 a1 = *(const float4*)(qt + kk * 16 + ty * 8 + 4);
            float4 b0 = *(const float4*)(kt + buf * 8192 + s * 2048 + tx * 8);
            float4 b1 = *(const float4*)(kt + buf * 8192 + s * 2048 + tx * 8 + 4);
            float av[8] = {a0.x, a0.y, a0.z, a0.w, a1.x, a1.y, a1.z, a1.w};
            float bv[8] = {b0.x, b0.y, b0.z, b0.w, b1.x, b1.y, b1.z, b1.w};
#pragma unroll
            for (int u = 0; u < 8; u++)
#pragma unroll
                for (int v = 0; v < 8; v++)
                    acc[u][v] = fmaf(av[u], bv[v], acc[u][v]);
        }
        // Stage next chunk into the other buffer, then barrier
        if (c + 1 < NCHUNK) {
            const int nb = (c + 1) & 1;
#pragma unroll
            for (int i = 0; i < 4; i++) {
                int j = tid + 512 * i;
                kt[nb * 8192 + 0 * 2048 + j] = pf[i].x;
                kt[nb * 8192 + 1 * 2048 + j] = pf[i].y;
                kt[nb * 8192 + 2 * 2048 + j] = pf[i].z;
                kt[nb * 8192 + 3 * 2048 + j] = pf[i].w;
            }
            __syncthreads();
        }
    }
    __syncthreads();   // all compute done before sc overwrites kt region

    // Mask + eps, write scores to smem
    const int* mb = amask + ((size_t)b * S_DIM + q0) * S_DIM;
#pragma unroll
    for (int u = 0; u < 8; u++) {
        int row = ty * 8 + u;
        int4 m0 = *(const int4*)(mb + (size_t)row * S_DIM + tx * 8);
        int4 m1 = *(const int4*)(mb + (size_t)row * S_DIM + tx * 8 + 4);
        float sv[8];
#pragma unroll
        for (int v = 0; v < 8; v++) {
            float s = acc[u][v];
            if (s == 0.0f) s = EPSV;
            sv[v] = s;
        }
        if (m0.x == 0) sv[0] = EPSV; if (m0.y == 0) sv[1] = EPSV;
        if (m0.z == 0) sv[2] = EPSV; if (m0.w == 0) sv[3] = EPSV;
        if (m1.x == 0) sv[4] = EPSV; if (m1.y == 0) sv[5] = EPSV;
        if (m1.z == 0) sv[6] = EPSV; if (m1.w == 0) sv[7] = EPSV;
        *(float4*)(sc + row * S_DIM + tx * 8)     = make_float4(sv[0], sv[1], sv[2], sv[3]);
        *(float4*)(sc + row * S_DIM + tx * 8 + 4) = make_float4(sv[4], sv[5], sv[6], sv[7]);
    }
    __syncthreads();

    // Softmax: warp w handles row w (16 warps, 16 rows). Exps kept in registers.
    {
        const int warp = tid >> 5;
        const int lane = tid & 31;
        const float* row = sc + warp * S_DIM;

        float4 x[16];
        float mx = -3.402823466e38f;
#pragma unroll
        for (int it = 0; it < 16; it++) {
            x[it] = *(const float4*)(row + (lane + 32 * it) * 4);
            mx = fmaxf(mx, fmaxf(fmaxf(x[it].x, x[it].y), fmaxf(x[it].z, x[it].w)));
        }
#pragma unroll
        for (int o = 16; o; o >>= 1) mx = fmaxf(mx, __shfl_xor_sync(0xffffffffu, mx, o));

        float sum = 0.0f;
#pragma unroll
        for (int it = 0; it < 16; it++) {
            x[it].x = __expf(x[it].x - mx);
            x[it].y = __expf(x[it].y - mx);
            x[it].z = __expf(x[it].z - mx);
            x[it].w = __expf(x[it].w - mx);
            sum += x[it].x + x[it].y + x[it].z + x[it].w;
        }
#pragma unroll
        for (int o = 16; o; o >>= 1) sum += __shfl_xor_sync(0xffffffffu, sum, o);
        const float inv = 1.0f / sum;

        float* wr = out_w + ((size_t)b * S_DIM + q0 + warp) * S_DIM;
#pragma unroll
        for (int it = 0; it < 16; it++) {
            float4 p = make_float4(x[it].x * inv, x[it].y * inv, x[it].z * inv, x[it].w * inv);
            *(float4*)(wr + (lane + 32 * it) * 4) = p;
        }
    }
}

// ---------------------------------------------------------------------------
// PV GEMM: out[b][i][d] = sum_j W[b][i][j] * V[b][j][d].
// Block = 32 rows x 64 cols, 128 threads, 4x4 thread tile, double-buffered
// smem (chunk = 16 j). Grid (64, 8) = 512 blocks -> multi-CTA occupancy.
// ---------------------------------------------------------------------------
#define PVCH 16

__global__ __launch_bounds__(128) void pv_kernel(
    const float* __restrict__ out_w, float* __restrict__ out_attn)
{
    __shared__ float wt[2 * PVCH * 36];   // [2][16][36] transposed W tile
    __shared__ float vt[2 * PVCH * 64];   // [2][16][64] V tile

    const int b   = blockIdx.y;
    const int r0  = blockIdx.x * 32;
    const int tid = threadIdx.x;
    const int tx  = tid & 15;    // cols tx*4..+3
    const int ty  = tid >> 4;    // rows ty*4..+3  (ty 0..7)

    const float* wb = out_w + ((size_t)b * S_DIM + r0) * S_DIM;
    const float* vb = g_v + (size_t)b * S_DIM * D_K;

    // load index assignments
    const int lw_r  = tid >> 2;         // 0..31
    const int lw_c4 = (tid & 3) * 4;    // 0,4,8,12
    const int lv_r  = tid >> 4;         // 0..7 (rows lv_r, lv_r+8)
    const int lv_c  = (tid & 15) * 4;

    float acc[4][4];
#pragma unroll
    for (int u = 0; u < 4; u++)
#pragma unroll
        for (int v = 0; v < 4; v++) acc[u][v] = 0.0f;

    // Prologue: chunk 0
    float4 pw = *(const float4*)(wb + (size_t)lw_r * S_DIM + lw_c4);
    float4 pv0 = *(const float4*)(vb + (size_t)lv_r * D_K + lv_c);
    float4 pv1 = *(const float4*)(vb + (size_t)(lv_r + 8) * D_K + lv_c);
    wt[(lw_c4 + 0) * 36 + lw_r] = pw.x;
    wt[(lw_c4 + 1) * 36 + lw_r] = pw.y;
    wt[(lw_c4 + 2) * 36 + lw_r] = pw.z;
    wt[(lw_c4 + 3) * 36 + lw_r] = pw.w;
    *(float4*)(vt + lv_r * 64 + lv_c)       = pv0;
    *(float4*)(vt + (lv_r + 8) * 64 + lv_c) = pv1;
    __syncthreads();

    const int NCH = S_DIM / PVCH;   // 128
    for (int c = 0; c < NCH; c++) {
        const int buf = c & 1;
        if (c + 1 < NCH) {
            int kk0 = (c + 1) * PVCH;
            pw  = *(const float4*)(wb + (size_t)lw_r * S_DIM + kk0 + lw_c4);
            pv0 = *(const float4*)(vb + (size_t)(kk0 + lv_r) * D_K + lv_c);
            pv1 = *(const float4*)(vb + (size_t)(kk0 + lv_r + 8) * D_K + lv_c);
        }
        const float* wtb = wt + buf * PVCH * 36;
        const float* vtb = vt + buf * PVCH * 64;
#pragma unroll
        for (int s = 0; s < PVCH; s++) {
            float4 a  = *(const float4*)(wtb + s * 36 + ty * 4);
            float4 v4 = *(const float4*)(vtb + s * 64 + tx * 4);
            acc[0][0] = fmaf(a.x, v4.x, acc[0][0]); acc[0][1] = fmaf(a.x, v4.y, acc[0][1]);
            acc[0][2] = fmaf(a.x, v4.z, acc[0][2]); acc[0][3] = fmaf(a.x, v4.w, acc[0][3]);
            acc[1][0] = fmaf(a.y, v4.x, acc[1][0]); acc[1][1] = fmaf(a.y, v4.y, acc[1][1]);
            acc[1][2] = fmaf(a.y, v4.z, acc[1][2]); acc[1][3] = fmaf(a.y, v4.w, acc[1][3]);
            acc[2][0] = fmaf(a.z, v4.x, acc[2][0]); acc[2][1] = fmaf(a.z, v4.y, acc[2][1]);
            acc[2][2] = fmaf(a.z, v4.z, acc[2][2]); acc[2][3] = fmaf(a.z, v4.w, acc[2][3]);
            acc[3][0] = fmaf(a.w, v4.x, acc[3][0]); acc[3][1] = fmaf(a.w, v4.y, acc[3][1]);
            acc[3][2] = fmaf(a.w, v4.z, acc[3][2]); acc[3][3] = fmaf(a.w, v4.w, acc[3][3]);
        }
        if (c + 1 < NCH) {
            const int nb = (c + 1) & 1;
            float* wtn = wt + nb * PVCH * 36;
            float* vtn = vt + nb * PVCH * 64;
            wtn[(lw_c4 + 0) * 36 + lw_r] = pw.x;
            wtn[(lw_c4 + 1) * 36 + lw_r] = pw.y;
            wtn[(lw_c4 + 2) * 36 + lw_r] = pw.z;
            wtn[(lw_c4 + 3) * 36 + lw_r] = pw.w;
            *(float4*)(vtn + lv_r * 64 + lv_c)       = pv0;
            *(float4*)(vtn + (lv_r + 8) * 64 + lv_c) = pv1;
        }
        __syncthreads();
    }

#pragma unroll
    for (int u = 0; u < 4; u++) {
        *(float4*)(out_attn + ((size_t)b * S_DIM + r0 + ty * 4 + u) * D_K + tx * 4) =
            make_float4(acc[u][0], acc[u][1], acc[u][2], acc[u][3]);
    }
}

// ---------------------------------------------------------------------------
extern "C" void kernel_launch(void* const* d_in, const int* in_sizes, int n_in,
                              void* d_out, int out_size)
{
    const float* query = (const float*)d_in[0];
    const float* key   = (const float*)d_in[1];
    const float* value = (const float*)d_in[2];
    const int*   amask = (const int*)d_in[3];
    const float* Wq = (const float*)d_in[4];
    const float* bq = (const float*)d_in[5];
    const float* Wk = (const float*)d_in[6];
    const float* bk = (const float*)d_in[7];
    const float* Wv = (const float*)d_in[8];
    const float* bv = (const float*)d_in[9];

    float* out_attn = (float*)d_out;                                // (B,S,64)
    float* out_w    = (float*)d_out + (size_t)B_DIM * S_DIM * D_K;  // (B,S,S)

    proj_kernel<<<dim3((B_DIM * S_DIM) / 64, 3), 256>>>(
        query, key, value, Wq, bq, Wk, bk, Wv, bv);

    const size_t smem = (size_t)(32768 + 1024) * sizeof(float);  // 135168 B
    cudaFuncSetAttribute(qk_softmax_kernel,
                         cudaFuncAttributeMaxDynamicSharedMemorySize, (int)smem);
    qk_softmax_kernel<<<dim3(S_DIM / 16, B_DIM), QK_THREADS, smem>>>(amask, out_w);

    pv_kernel<<<dim3(S_DIM / 32, B_DIM), 128>>>(out_w, out_attn);
}

// round 10
// speedup vs baseline: 2.3656x; 1.2566x over previous
#include <cuda_runtime.h>
#include <math.h>
#include <stdint.h>

#define B_DIM 8
#define S_DIM 2048
#define D_MODEL 512
#define D_K 64
#define EPSV 1e-6f

// Scratch for projected q (pre-scaled by dk^-0.5), k, v
__device__ float g_q[B_DIM * S_DIM * D_K];
__device__ float g_k[B_DIM * S_DIM * D_K];
__device__ float g_v[B_DIM * S_DIM * D_K];

// ---------------- tf32 MMA helpers ----------------
__device__ __forceinline__ unsigned f2tf32(float f) {
    unsigned r;
    asm("cvt.rna.tf32.f32 %0, %1;" : "=r"(r) : "f"(f));
    return r;
}
__device__ __forceinline__ void mma_tf32(float* d, const unsigned* a, const unsigned* b) {
    asm volatile(
        "mma.sync.aligned.m16n8k8.row.col.f32.tf32.tf32.f32 "
        "{%0,%1,%2,%3}, {%4,%5,%6,%7}, {%8,%9}, {%0,%1,%2,%3};"
        : "+f"(d[0]), "+f"(d[1]), "+f"(d[2]), "+f"(d[3])
        : "r"(a[0]), "r"(a[1]), "r"(a[2]), "r"(a[3]), "r"(b[0]), "r"(b[1]));
}
#define CP16(dst_u32, src_ptr) \
    asm volatile("cp.async.ca.shared.global [%0], [%1], 16;" :: "r"(dst_u32), "l"(src_ptr))
#define CPCOMMIT() asm volatile("cp.async.commit_group;")
#define CPWAIT0()  asm volatile("cp.async.wait_group 0;")
#define CPWAIT1()  asm volatile("cp.async.wait_group 1;")

// ---------------------------------------------------------------------------
// Projection (unchanged): Out[r][d] = (X[r]·W[d] + bias[d]) * scale
// ---------------------------------------------------------------------------
__global__ __launch_bounds__(256) void proj_kernel(
    const float* __restrict__ Xq, const float* __restrict__ Xk, const float* __restrict__ Xv,
    const float* __restrict__ Wq, const float* __restrict__ bq,
    const float* __restrict__ Wk, const float* __restrict__ bk,
    const float* __restrict__ Wv, const float* __restrict__ bv)
{
    const float* X; const float* W; const float* bias; float* Out; float scale;
    if (blockIdx.y == 0)      { X = Xq; W = Wq; bias = bq; Out = g_q; scale = 0.125f; }
    else if (blockIdx.y == 1) { X = Xk; W = Wk; bias = bk; Out = g_k; scale = 1.0f; }
    else                      { X = Xv; W = Wv; bias = bv; Out = g_v; scale = 1.0f; }

    __shared__ float Xs[64 * 17];
    __shared__ float Ws[64 * 17];

    const int t  = threadIdx.x;
    const int tx = t & 15;
    const int ty = t >> 4;
    const int rowBase = blockIdx.x * 64;
    const int lrow = t >> 2;
    const int lk   = (t & 3) * 4;

    float acc[4][4];
#pragma unroll
    for (int u = 0; u < 4; u++)
#pragma unroll
        for (int v = 0; v < 4; v++) acc[u][v] = 0.0f;

    for (int k0 = 0; k0 < D_MODEL; k0 += 16) {
        float4 xv = *(const float4*)(X + (size_t)(rowBase + lrow) * D_MODEL + k0 + lk);
        float4 wv = *(const float4*)(W + (size_t)lrow * D_MODEL + k0 + lk);
        __syncthreads();
        Xs[lrow * 17 + lk + 0] = xv.x; Xs[lrow * 17 + lk + 1] = xv.y;
        Xs[lrow * 17 + lk + 2] = xv.z; Xs[lrow * 17 + lk + 3] = xv.w;
        Ws[lrow * 17 + lk + 0] = wv.x; Ws[lrow * 17 + lk + 1] = wv.y;
        Ws[lrow * 17 + lk + 2] = wv.z; Ws[lrow * 17 + lk + 3] = wv.w;
        __syncthreads();
#pragma unroll
        for (int kk = 0; kk < 16; kk++) {
            float a0 = Xs[(ty * 4 + 0) * 17 + kk];
            float a1 = Xs[(ty * 4 + 1) * 17 + kk];
            float a2 = Xs[(ty * 4 + 2) * 17 + kk];
            float a3 = Xs[(ty * 4 + 3) * 17 + kk];
            float b0 = Ws[(tx * 4 + 0) * 17 + kk];
            float b1 = Ws[(tx * 4 + 1) * 17 + kk];
            float b2 = Ws[(tx * 4 + 2) * 17 + kk];
            float b3 = Ws[(tx * 4 + 3) * 17 + kk];
            acc[0][0] = fmaf(a0, b0, acc[0][0]); acc[0][1] = fmaf(a0, b1, acc[0][1]);
            acc[0][2] = fmaf(a0, b2, acc[0][2]); acc[0][3] = fmaf(a0, b3, acc[0][3]);
            acc[1][0] = fmaf(a1, b0, acc[1][0]); acc[1][1] = fmaf(a1, b1, acc[1][1]);
            acc[1][2] = fmaf(a1, b2, acc[1][2]); acc[1][3] = fmaf(a1, b3, acc[1][3]);
            acc[2][0] = fmaf(a2, b0, acc[2][0]); acc[2][1] = fmaf(a2, b1, acc[2][1]);
            acc[2][2] = fmaf(a2, b2, acc[2][2]); acc[2][3] = fmaf(a2, b3, acc[2][3]);
            acc[3][0] = fmaf(a3, b0, acc[3][0]); acc[3][1] = fmaf(a3, b1, acc[3][1]);
            acc[3][2] = fmaf(a3, b2, acc[3][2]); acc[3][3] = fmaf(a3, b3, acc[3][3]);
        }
    }

#pragma unroll
    for (int u = 0; u < 4; u++) {
        int r = rowBase + ty * 4 + u;
#pragma unroll
        for (int v = 0; v < 4; v++) {
            int c = tx * 4 + v;
            Out[(size_t)r * D_K + c] = (acc[u][v] + bias[c]) * scale;
        }
    }
}

// ---------------------------------------------------------------------------
// QK^T (tf32 MMA) + mask + softmax. Block = (batch, 16 q rows) x 2048 cols.
// 512 threads = 16 warps; warp w owns cols [w*128, w*128+128).
// Computes S^T in m16n8k8 tiles: A = K tile (16 j x 8 d), B = Q (8 d x 8 i).
// K staged in smem [2][2048][12] via cp.async double-buffer, 8 chunks of 8 d.
// Scores -> smem sc[16][2052] (aliases kt) -> per-row softmax -> weights out.
// smem: kt 2*2048*12 = 49152 fl (196608 B), qs[16][68] at +49152. 200960 B.
// ---------------------------------------------------------------------------
__global__ __launch_bounds__(512, 1) void qk_softmax_kernel(
    const int* __restrict__ amask, float* __restrict__ out_w)
{
    extern __shared__ float sh[];
    float* kt = sh;               // [2][2048][12]
    float* sc = sh;               // [16][2052] (alias, used after compute)
    float* qs = sh + 49152;       // [16][68]

    const int b    = blockIdx.y;
    const int q0   = blockIdx.x * 16;
    const int tid  = threadIdx.x;
    const int w    = tid >> 5;
    const int lane = tid & 31;
    const int g    = lane >> 2;   // groupID
    const int tig  = lane & 3;    // thread-in-group

    // Stage q tile (16 x 64) into qs, stride 68 (conflict-free for B frags)
    {
        int r  = tid & 15;
        int kk = (tid >> 4) * 2;
        const float* qsrc = g_q + ((size_t)b * S_DIM + q0 + r) * D_K + kk;
        qs[r * 68 + kk]     = qsrc[0];
        qs[r * 68 + kk + 1] = qsrc[1];
    }

    const float* kb = g_k + (size_t)b * S_DIM * D_K;
    const uint32_t kt_u32 = (uint32_t)__cvta_generic_to_shared(kt);
    const int jrow = tid >> 1;          // 0..255
    const int loff = (tid & 1) * 4;     // 0 or 4

    float acc[8][2][4];
#pragma unroll
    for (int jt = 0; jt < 8; jt++)
#pragma unroll
        for (int it = 0; it < 2; it++)
#pragma unroll
            for (int e = 0; e < 4; e++) acc[jt][it][e] = 0.0f;

    // Prologue: async-load chunk 0 (d = 0..7 for all 2048 j)
#pragma unroll
    for (int ii = 0; ii < 8; ii++) {
        int j = jrow + 256 * ii;
        CP16(kt_u32 + (uint32_t)(j * 12 + loff) * 4, kb + (size_t)j * D_K + loff);
    }
    CPCOMMIT();

    for (int c = 0; c < 8; c++) {
        if (c < 7) {
            uint32_t base = kt_u32 + (uint32_t)(((c + 1) & 1) * 24576) * 4;
#pragma unroll
            for (int ii = 0; ii < 8; ii++) {
                int j = jrow + 256 * ii;
                CP16(base + (uint32_t)(j * 12 + loff) * 4,
                     kb + (size_t)j * D_K + (c + 1) * 8 + loff);
            }
            CPCOMMIT();
            CPWAIT1();
        } else {
            CPWAIT0();
        }
        __syncthreads();

        // B fragments for this chunk (q): b0 at (k=tig, n=g), b1 at (k=tig+4, n=g)
        unsigned bf[2][2];
#pragma unroll
        for (int it = 0; it < 2; it++) {
            bf[it][0] = f2tf32(qs[(it * 8 + g) * 68 + c * 8 + tig]);
            bf[it][1] = f2tf32(qs[(it * 8 + g) * 68 + c * 8 + tig + 4]);
        }

        const float* kbuf = kt + (c & 1) * 24576;
#pragma unroll
        for (int jt = 0; jt < 8; jt++) {
            int jr = w * 128 + jt * 16 + g;
            unsigned af[4];
            af[0] = f2tf32(kbuf[jr * 12 + tig]);
            af[1] = f2tf32(kbuf[(jr + 8) * 12 + tig]);
            af[2] = f2tf32(kbuf[jr * 12 + tig + 4]);
            af[3] = f2tf32(kbuf[(jr + 8) * 12 + tig + 4]);
            mma_tf32(acc[jt][0], af, bf[0]);
            mma_tf32(acc[jt][1], af, bf[1]);
        }
        __syncthreads();   // buffer reuse guard (also guards sc alias after loop)
    }

    // Mask + eps, scatter S^T fragments into sc[i][j] (stride 2052: conflict-free)
    const int* mb = amask + ((size_t)b * S_DIM + q0) * S_DIM;
#pragma unroll
    for (int jt = 0; jt < 8; jt++) {
        int j0 = w * 128 + jt * 16 + g;
#pragma unroll
        for (int it = 0; it < 2; it++) {
            int i0 = it * 8 + tig * 2;
#pragma unroll
            for (int e = 0; e < 4; e++) {
                int i = i0 + (e & 1);
                int j = j0 + (e >= 2 ? 8 : 0);
                float s = acc[jt][it][e];
                if (s == 0.0f) s = EPSV;
                if (mb[(size_t)i * S_DIM + j] == 0) s = EPSV;
                sc[i * 2052 + j] = s;
            }
        }
    }
    __syncthreads();

    // Softmax: warp w handles row w. Exps kept in registers; weights to gmem.
    {
        const float* row = sc + w * 2052;
        float4 x[16];
        float mx = -3.402823466e38f;
#pragma unroll
        for (int it = 0; it < 16; it++) {
            x[it] = *(const float4*)(row + (lane + 32 * it) * 4);
            mx = fmaxf(mx, fmaxf(fmaxf(x[it].x, x[it].y), fmaxf(x[it].z, x[it].w)));
        }
#pragma unroll
        for (int o = 16; o; o >>= 1) mx = fmaxf(mx, __shfl_xor_sync(0xffffffffu, mx, o));

        float sum = 0.0f;
#pragma unroll
        for (int it = 0; it < 16; it++) {
            x[it].x = __expf(x[it].x - mx);
            x[it].y = __expf(x[it].y - mx);
            x[it].z = __expf(x[it].z - mx);
            x[it].w = __expf(x[it].w - mx);
            sum += x[it].x + x[it].y + x[it].z + x[it].w;
        }
#pragma unroll
        for (int o = 16; o; o >>= 1) sum += __shfl_xor_sync(0xffffffffu, sum, o);
        const float inv = 1.0f / sum;

        float* wr = out_w + ((size_t)b * S_DIM + q0 + w) * S_DIM;
#pragma unroll
        for (int it = 0; it < 16; it++) {
            *(float4*)(wr + (lane + 32 * it) * 4) =
                make_float4(x[it].x * inv, x[it].y * inv, x[it].z * inv, x[it].w * inv);
        }
    }
}

// ---------------------------------------------------------------------------
// PV (tf32 MMA): out[i][d] = sum_j P[i][j] V[j][d].
// Block = 64 rows x 64 cols, 128 threads = 4 warps (warp w owns 16 rows).
// Chunk = 32 j, cp.async double-buffered: pt[2][64][36], vt[2][32][72].
// ---------------------------------------------------------------------------
__global__ __launch_bounds__(128, 2) void pv_kernel(
    const float* __restrict__ out_w, float* __restrict__ out_attn)
{
    __shared__ float pt[2 * 64 * 36];   // P tile, stride 36 (conflict-free A frags)
    __shared__ float vt[2 * 32 * 72];   // V tile, stride 72 (conflict-free B frags)

    const int b    = blockIdx.y;
    const int r0   = blockIdx.x * 64;
    const int tid  = threadIdx.x;
    const int w    = tid >> 5;
    const int lane = tid & 31;
    const int g    = lane >> 2;
    const int tig  = lane & 3;

    const float* wb = out_w + ((size_t)b * S_DIM + r0) * S_DIM;
    const float* vb = g_v + (size_t)b * S_DIM * D_K;
    const uint32_t pt_u32 = (uint32_t)__cvta_generic_to_shared(pt);
    const uint32_t vt_u32 = (uint32_t)__cvta_generic_to_shared(vt);

    // loader indices
    const int p_i   = tid >> 1;          // 0..63
    const int p_off = (tid & 1) * 16;    // 0 or 16 (floats)
    const int v_j   = tid >> 2;          // 0..31
    const int v_f4  = tid & 3;           // 0..3

    float acc[8][4];
#pragma unroll
    for (int nt = 0; nt < 8; nt++)
#pragma unroll
        for (int e = 0; e < 4; e++) acc[nt][e] = 0.0f;

    // Prologue: chunk 0
#pragma unroll
    for (int k = 0; k < 4; k++)
        CP16(pt_u32 + (uint32_t)(p_i * 36 + p_off + k * 4) * 4,
             wb + (size_t)p_i * S_DIM + p_off + k * 4);
#pragma unroll
    for (int k = 0; k < 4; k++)
        CP16(vt_u32 + (uint32_t)(v_j * 72 + (v_f4 + 4 * k) * 4) * 4,
             vb + (size_t)v_j * D_K + (v_f4 + 4 * k) * 4);
    CPCOMMIT();

    const int NCH = S_DIM / 32;   // 64
    for (int c = 0; c < NCH; c++) {
        if (c + 1 < NCH) {
            uint32_t pbase = pt_u32 + (uint32_t)(((c + 1) & 1) * 64 * 36) * 4;
            uint32_t vbase = vt_u32 + (uint32_t)(((c + 1) & 1) * 32 * 72) * 4;
            int j0 = (c + 1) * 32;
#pragma unroll
            for (int k = 0; k < 4; k++)
                CP16(pbase + (uint32_t)(p_i * 36 + p_off + k * 4) * 4,
                     wb + (size_t)p_i * S_DIM + j0 + p_off + k * 4);
#pragma unroll
            for (int k = 0; k < 4; k++)
                CP16(vbase + (uint32_t)(v_j * 72 + (v_f4 + 4 * k) * 4) * 4,
                     vb + (size_t)(j0 + v_j) * D_K + (v_f4 + 4 * k) * 4);
            CPCOMMIT();
            CPWAIT1();
        } else {
            CPWAIT0();
        }
        __syncthreads();

        const float* pb = pt + (c & 1) * 64 * 36;
        const float* vv = vt + (c & 1) * 32 * 72;
        const int ir = w * 16 + g;
#pragma unroll
        for (int ks = 0; ks < 4; ks++) {
            unsigned af[4];
            af[0] = f2tf32(pb[ir * 36 + ks * 8 + tig]);
            af[1] = f2tf32(pb[(ir + 8) * 36 + ks * 8 + tig]);
            af[2] = f2tf32(pb[ir * 36 + ks * 8 + tig + 4]);
            af[3] = f2tf32(pb[(ir + 8) * 36 + ks * 8 + tig + 4]);
#pragma unroll
            for (int nt = 0; nt < 8; nt++) {
                unsigned bf[2];
                bf[0] = f2tf32(vv[(ks * 8 + tig) * 72 + nt * 8 + g]);
                bf[1] = f2tf32(vv[(ks * 8 + tig + 4) * 72 + nt * 8 + g]);
                mma_tf32(acc[nt], af, bf);
            }
        }
        __syncthreads();
    }

    // Epilogue: D frag (i = w*16 + g (+8), d = nt*8 + tig*2 (+1)) -> float2 stores
    float* ob = out_attn + ((size_t)b * S_DIM + r0) * D_K;
#pragma unroll
    for (int nt = 0; nt < 8; nt++) {
        int d = nt * 8 + tig * 2;
        int i = w * 16 + g;
        *(float2*)(ob + (size_t)i * D_K + d)       = make_float2(acc[nt][0], acc[nt][1]);
        *(float2*)(ob + (size_t)(i + 8) * D_K + d) = make_float2(acc[nt][2], acc[nt][3]);
    }
}

// ---------------------------------------------------------------------------
extern "C" void kernel_launch(void* const* d_in, const int* in_sizes, int n_in,
                              void* d_out, int out_size)
{
    const float* query = (const float*)d_in[0];
    const float* key   = (const float*)d_in[1];
    const float* value = (const float*)d_in[2];
    const int*   amask = (const int*)d_in[3];
    const float* Wq = (const float*)d_in[4];
    const float* bq = (const float*)d_in[5];
    const float* Wk = (const float*)d_in[6];
    const float* bk = (const float*)d_in[7];
    const float* Wv = (const float*)d_in[8];
    const float* bv = (const float*)d_in[9];

    float* out_attn = (float*)d_out;                                // (B,S,64)
    float* out_w    = (float*)d_out + (size_t)B_DIM * S_DIM * D_K;  // (B,S,S)

    proj_kernel<<<dim3((B_DIM * S_DIM) / 64, 3), 256>>>(
        query, key, value, Wq, bq, Wk, bk, Wv, bv);

    const size_t smem = (size_t)(49152 + 16 * 68) * sizeof(float);  // 200960 B
    cudaFuncSetAttribute(qk_softmax_kernel,
                         cudaFuncAttributeMaxDynamicSharedMemorySize, (int)smem);
    qk_softmax_kernel<<<dim3(S_DIM / 16, B_DIM), 512, smem>>>(amask, out_w);

    pv_kernel<<<dim3(S_DIM / 64, B_DIM), 128>>>(out_w, out_attn);
}

// round 12
// speedup vs baseline: 3.0869x; 1.3049x over previous
#include <cuda_runtime.h>
#include <math.h>
#include <stdint.h>

#define B_DIM 8
#define S_DIM 2048
#define D_MODEL 512
#define D_K 64
#define EPSV 1e-6f

// Scratch for projected q (pre-scaled by dk^-0.5), k, v — stored TF32-ROUNDED
__device__ float g_q[B_DIM * S_DIM * D_K];
__device__ float g_k[B_DIM * S_DIM * D_K];
__device__ float g_v[B_DIM * S_DIM * D_K];

// ---------------- tf32 MMA helpers ----------------
__device__ __forceinline__ unsigned f2tf32(float f) {
    unsigned r;
    asm("cvt.rna.tf32.f32 %0, %1;" : "=r"(r) : "f"(f));
    return r;
}
__device__ __forceinline__ void mma_tf32(float* d, const unsigned* a, const unsigned* b) {
    asm volatile(
        "mma.sync.aligned.m16n8k8.row.col.f32.tf32.tf32.f32 "
        "{%0,%1,%2,%3}, {%4,%5,%6,%7}, {%8,%9}, {%0,%1,%2,%3};"
        : "+f"(d[0]), "+f"(d[1]), "+f"(d[2]), "+f"(d[3])
        : "r"(a[0]), "r"(a[1]), "r"(a[2]), "r"(a[3]), "r"(b[0]), "r"(b[1]));
}
#define CP16(dst_u32, src_ptr) \
    asm volatile("cp.async.ca.shared.global [%0], [%1], 16;" :: "r"(dst_u32), "l"(src_ptr))
#define CPCOMMIT() asm volatile("cp.async.commit_group;")
#define CPWAIT0()  asm volatile("cp.async.wait_group 0;")
#define CPWAIT1()  asm volatile("cp.async.wait_group 1;")

// ---------------------------------------------------------------------------
// Projection via tf32 MMA: Out[r][d] = tf32_round((X[r]·W[d] + bias[d])*scale)
// Block: 256 rows x 64 cols, 256 thr = 8 warps; warp = 32 rows (2 m16 tiles)
// x 64 cols (8 n8 tiles). K chunks of 16, cp.async double-buffered.
// smem (dynamic): Xs[2][256][20], Ws[2][64][20]  (stride 20 = conflict-free)
// ---------------------------------------------------------------------------
#define PJ_XST 20
#define PJ_XBUF (256 * PJ_XST)
#define PJ_WBUF (64 * PJ_XST)

__global__ __launch_bounds__(256, 1) void proj_mma_kernel(
    const float* __restrict__ Xq, const float* __restrict__ Xk, const float* __restrict__ Xv,
    const float* __restrict__ Wq, const float* __restrict__ bq,
    const float* __restrict__ Wk, const float* __restrict__ bk,
    const float* __restrict__ Wv, const float* __restrict__ bv)
{
    const float* X; const float* W; const float* bias; float* Out; float scale;
    if (blockIdx.y == 0)      { X = Xq; W = Wq; bias = bq; Out = g_q; scale = 0.125f; }
    else if (blockIdx.y == 1) { X = Xk; W = Wk; bias = bk; Out = g_k; scale = 1.0f; }
    else                      { X = Xv; W = Wv; bias = bv; Out = g_v; scale = 1.0f; }

    extern __shared__ float psh[];
    float* Xs = psh;                       // [2][256][20]
    float* Ws = psh + 2 * PJ_XBUF;         // [2][64][20]

    const int tid  = threadIdx.x;
    const int w    = tid >> 5;
    const int lane = tid & 31;
    const int g    = lane >> 2;
    const int tig  = lane & 3;
    const int r0   = blockIdx.x * 256;

    const uint32_t xs_u32 = (uint32_t)__cvta_generic_to_shared(Xs);
    const uint32_t ws_u32 = (uint32_t)__cvta_generic_to_shared(Ws);

    // loaders: X — 2 threads/row (32B each), 128 rows x 2 iterations
    const int xl_r   = tid >> 1;          // 0..127
    const int xl_off = (tid & 1) * 8;     // 0 or 8 floats
    // W — 4 threads/row (16B each), 64 rows
    const int wl_n  = tid >> 2;           // 0..63
    const int wl_k4 = (tid & 3) * 4;      // 0,4,8,12

    float acc[2][8][4];
#pragma unroll
    for (int mt = 0; mt < 2; mt++)
#pragma unroll
        for (int nt = 0; nt < 8; nt++)
#pragma unroll
            for (int e = 0; e < 4; e++) acc[mt][nt][e] = 0.0f;

    // Prologue: chunk 0
#pragma unroll
    for (int it = 0; it < 2; it++) {
        int r = xl_r + it * 128;
#pragma unroll
        for (int h = 0; h < 2; h++)
            CP16(xs_u32 + (uint32_t)(r * PJ_XST + xl_off + h * 4) * 4,
                 X + (size_t)(r0 + r) * D_MODEL + xl_off + h * 4);
    }
    CP16(ws_u32 + (uint32_t)(wl_n * PJ_XST + wl_k4) * 4,
         W + (size_t)wl_n * D_MODEL + wl_k4);
    CPCOMMIT();

    const int NCH = D_MODEL / 16;   // 32
    for (int c = 0; c < NCH; c++) {
        if (c + 1 < NCH) {
            int k0 = (c + 1) * 16;
            uint32_t xb = xs_u32 + (uint32_t)(((c + 1) & 1) * PJ_XBUF) * 4;
            uint32_t wbb = ws_u32 + (uint32_t)(((c + 1) & 1) * PJ_WBUF) * 4;
#pragma unroll
            for (int it = 0; it < 2; it++) {
                int r = xl_r + it * 128;
#pragma unroll
                for (int h = 0; h < 2; h++)
                    CP16(xb + (uint32_t)(r * PJ_XST + xl_off + h * 4) * 4,
                         X + (size_t)(r0 + r) * D_MODEL + k0 + xl_off + h * 4);
            }
            CP16(wbb + (uint32_t)(wl_n * PJ_XST + wl_k4) * 4,
                 W + (size_t)wl_n * D_MODEL + k0 + wl_k4);
            CPCOMMIT();
            CPWAIT1();
        } else {
            CPWAIT0();
        }
        __syncthreads();

        const float* xb = Xs + (c & 1) * PJ_XBUF;
        const float* wb = Ws + (c & 1) * PJ_WBUF;
#pragma unroll
        for (int ks = 0; ks < 2; ks++) {
            const int kk = ks * 8;
            unsigned af[2][4];
#pragma unroll
            for (int mt = 0; mt < 2; mt++) {
                int rb = w * 32 + mt * 16 + g;
                af[mt][0] = f2tf32(xb[rb * PJ_XST + kk + tig]);
                af[mt][1] = f2tf32(xb[(rb + 8) * PJ_XST + kk + tig]);
                af[mt][2] = f2tf32(xb[rb * PJ_XST + kk + tig + 4]);
                af[mt][3] = f2tf32(xb[(rb + 8) * PJ_XST + kk + tig + 4]);
            }
#pragma unroll
            for (int nt = 0; nt < 8; nt++) {
                unsigned bf[2];
                bf[0] = f2tf32(wb[(nt * 8 + g) * PJ_XST + kk + tig]);
                bf[1] = f2tf32(wb[(nt * 8 + g) * PJ_XST + kk + tig + 4]);
                mma_tf32(acc[0][nt], af[0], bf);
                mma_tf32(acc[1][nt], af[1], bf);
            }
        }
        __syncthreads();
    }

    // Epilogue: (acc + bias) * scale, tf32-round, float2 stores
#pragma unroll
    for (int nt = 0; nt < 8; nt++) {
        int d = nt * 8 + tig * 2;
        float b0 = __ldg(bias + d), b1 = __ldg(bias + d + 1);
#pragma unroll
        for (int mt = 0; mt < 2; mt++) {
            int i = r0 + w * 32 + mt * 16 + g;
            float v0 = (acc[mt][nt][0] + b0) * scale;
            float v1 = (acc[mt][nt][1] + b1) * scale;
            float v2 = (acc[mt][nt][2] + b0) * scale;
            float v3 = (acc[mt][nt][3] + b1) * scale;
            *(float2*)(Out + (size_t)i * D_K + d) =
                make_float2(__uint_as_float(f2tf32(v0)), __uint_as_float(f2tf32(v1)));
            *(float2*)(Out + (size_t)(i + 8) * D_K + d) =
                make_float2(__uint_as_float(f2tf32(v2)), __uint_as_float(f2tf32(v3)));
        }
    }
}

// ---------------------------------------------------------------------------
// QK^T (tf32 MMA) + mask + softmax. Operands pre-rounded -> raw bit loads.
// Block = (batch, 16 q rows) x 2048 cols, 512 thr = 16 warps.
// ---------------------------------------------------------------------------
__global__ __launch_bounds__(512, 1) void qk_softmax_kernel(
    const int* __restrict__ amask, float* __restrict__ out_w)
{
    extern __shared__ float sh[];
    float* kt = sh;               // [2][2048][12]
    float* sc = sh;               // [16][2052] (alias, used after compute)
    float* qs = sh + 49152;       // [16][68]

    const int b    = blockIdx.y;
    const int q0   = blockIdx.x * 16;
    const int tid  = threadIdx.x;
    const int w    = tid >> 5;
    const int lane = tid & 31;
    const int g    = lane >> 2;
    const int tig  = lane & 3;

    // Stage q tile (16 x 64) into qs, stride 68
    {
        int r  = tid & 15;
        int kk = (tid >> 4) * 2;
        const float* qsrc = g_q + ((size_t)b * S_DIM + q0 + r) * D_K + kk;
        qs[r * 68 + kk]     = qsrc[0];
        qs[r * 68 + kk + 1] = qsrc[1];
    }

    const float* kb = g_k + (size_t)b * S_DIM * D_K;
    const uint32_t kt_u32 = (uint32_t)__cvta_generic_to_shared(kt);
    const int jrow = tid >> 1;
    const int loff = (tid & 1) * 4;

    float acc[8][2][4];
#pragma unroll
    for (int jt = 0; jt < 8; jt++)
#pragma unroll
        for (int it = 0; it < 2; it++)
#pragma unroll
            for (int e = 0; e < 4; e++) acc[jt][it][e] = 0.0f;

#pragma unroll
    for (int ii = 0; ii < 8; ii++) {
        int j = jrow + 256 * ii;
        CP16(kt_u32 + (uint32_t)(j * 12 + loff) * 4, kb + (size_t)j * D_K + loff);
    }
    CPCOMMIT();

    for (int c = 0; c < 8; c++) {
        if (c < 7) {
            uint32_t base = kt_u32 + (uint32_t)(((c + 1) & 1) * 24576) * 4;
#pragma unroll
            for (int ii = 0; ii < 8; ii++) {
                int j = jrow + 256 * ii;
                CP16(base + (uint32_t)(j * 12 + loff) * 4,
                     kb + (size_t)j * D_K + (c + 1) * 8 + loff);
            }
            CPCOMMIT();
            CPWAIT1();
        } else {
            CPWAIT0();
        }
        __syncthreads();

        // B fragments (q, pre-rounded -> raw bits)
        unsigned bf[2][2];
#pragma unroll
        for (int it = 0; it < 2; it++) {
            bf[it][0] = __float_as_uint(qs[(it * 8 + g) * 68 + c * 8 + tig]);
            bf[it][1] = __float_as_uint(qs[(it * 8 + g) * 68 + c * 8 + tig + 4]);
        }

        const float* kbuf = kt + (c & 1) * 24576;
#pragma unroll
        for (int jt = 0; jt < 8; jt++) {
            int jr = w * 128 + jt * 16 + g;
            unsigned af[4];
            af[0] = __float_as_uint(kbuf[jr * 12 + tig]);
            af[1] = __float_as_uint(kbuf[(jr + 8) * 12 + tig]);
            af[2] = __float_as_uint(kbuf[jr * 12 + tig + 4]);
            af[3] = __float_as_uint(kbuf[(jr + 8) * 12 + tig + 4]);
            mma_tf32(acc[jt][0], af, bf[0]);
            mma_tf32(acc[jt][1], af, bf[1]);
        }
        __syncthreads();
    }

    // Mask + eps, scatter S^T fragments into sc[i][j]
    const int* mb = amask + ((size_t)b * S_DIM + q0) * S_DIM;
#pragma unroll
    for (int jt = 0; jt < 8; jt++) {
        int j0 = w * 128 + jt * 16 + g;
#pragma unroll
        for (int it = 0; it < 2; it++) {
            int i0 = it * 8 + tig * 2;
#pragma unroll
            for (int e = 0; e < 4; e++) {
                int i = i0 + (e & 1);
                int j = j0 + (e >= 2 ? 8 : 0);
                float s = acc[jt][it][e];
                if (s == 0.0f) s = EPSV;
                if (mb[(size_t)i * S_DIM + j] == 0) s = EPSV;
                sc[i * 2052 + j] = s;
            }
        }
    }
    __syncthreads();

    // Softmax: warp w handles row w
    {
        const float* row = sc + w * 2052;
        float4 x[16];
        float mx = -3.402823466e38f;
#pragma unroll
        for (int it = 0; it < 16; it++) {
            x[it] = *(const float4*)(row + (lane + 32 * it) * 4);
            mx = fmaxf(mx, fmaxf(fmaxf(x[it].x, x[it].y), fmaxf(x[it].z, x[it].w)));
        }
#pragma unroll
        for (int o = 16; o; o >>= 1) mx = fmaxf(mx, __shfl_xor_sync(0xffffffffu, mx, o));

        float sum = 0.0f;
#pragma unroll
        for (int it = 0; it < 16; it++) {
            x[it].x = __expf(x[it].x - mx);
            x[it].y = __expf(x[it].y - mx);
            x[it].z = __expf(x[it].z - mx);
            x[it].w = __expf(x[it].w - mx);
            sum += x[it].x + x[it].y + x[it].z + x[it].w;
        }
#pragma unroll
        for (int o = 16; o; o >>= 1) sum += __shfl_xor_sync(0xffffffffu, sum, o);
        const float inv = 1.0f / sum;

        float* wr = out_w + ((size_t)b * S_DIM + q0 + w) * S_DIM;
#pragma unroll
        for (int it = 0; it < 16; it++) {
            *(float4*)(wr + (lane + 32 * it) * 4) =
                make_float4(x[it].x * inv, x[it].y * inv, x[it].z * inv, x[it].w * inv);
        }
    }
}

// ---------------------------------------------------------------------------
// PV (tf32 MMA): V pre-rounded (raw bits), P truncated (raw bits).
// ---------------------------------------------------------------------------
__global__ __launch_bounds__(128, 2) void pv_kernel(
    const float* __restrict__ out_w, float* __restrict__ out_attn)
{
    __shared__ float pt[2 * 64 * 36];
    __shared__ float vt[2 * 32 * 72];

    const int b    = blockIdx.y;
    const int r0   = blockIdx.x * 64;
    const int tid  = threadIdx.x;
    const int w    = tid >> 5;
    const int lane = tid & 31;
    const int g    = lane >> 2;
    const int tig  = lane & 3;

    const float* wb = out_w + ((size_t)b * S_DIM + r0) * S_DIM;
    const float* vb = g_v + (size_t)b * S_DIM * D_K;
    const uint32_t pt_u32 = (uint32_t)__cvta_generic_to_shared(pt);
    const uint32_t vt_u32 = (uint32_t)__cvta_generic_to_shared(vt);

    const int p_i   = tid >> 1;
    const int p_off = (tid & 1) * 16;
    const int v_j   = tid >> 2;
    const int v_f4  = tid & 3;

    float acc[8][4];
#pragma unroll
    for (int nt = 0; nt < 8; nt++)
#pragma unroll
        for (int e = 0; e < 4; e++) acc[nt][e] = 0.0f;

#pragma unroll
    for (int k = 0; k < 4; k++)
        CP16(pt_u32 + (uint32_t)(p_i * 36 + p_off + k * 4) * 4,
             wb + (size_t)p_i * S_DIM + p_off + k * 4);
#pragma unroll
    for (int k = 0; k < 4; k++)
        CP16(vt_u32 + (uint32_t)(v_j * 72 + (v_f4 + 4 * k) * 4) * 4,
             vb + (size_t)v_j * D_K + (v_f4 + 4 * k) * 4);
    CPCOMMIT();

    const int NCH = S_DIM / 32;
    for (int c = 0; c < NCH; c++) {
        if (c + 1 < NCH) {
            uint32_t pbase = pt_u32 + (uint32_t)(((c + 1) & 1) * 64 * 36) * 4;
            uint32_t vbase = vt_u32 + (uint32_t)(((c + 1) & 1) * 32 * 72) * 4;
            int j0 = (c + 1) * 32;
#pragma unroll
            for (int k = 0; k < 4; k++)
                CP16(pbase + (uint32_t)(p_i * 36 + p_off + k * 4) * 4,
                     wb + (size_t)p_i * S_DIM + j0 + p_off + k * 4);
#pragma unroll
            for (int k = 0; k < 4; k++)
                CP16(vbase + (uint32_t)(v_j * 72 + (v_f4 + 4 * k) * 4) * 4,
                     vb + (size_t)(j0 + v_j) * D_K + (v_f4 + 4 * k) * 4);
            CPCOMMIT();
            CPWAIT1();
        } else {
            CPWAIT0();
        }
        __syncthreads();

        const float* pb = pt + (c & 1) * 64 * 36;
        const float* vv = vt + (c & 1) * 32 * 72;
        const int ir = w * 16 + g;
#pragma unroll
        for (int ks = 0; ks < 4; ks++) {
            unsigned af[4];
            af[0] = __float_as_uint(pb[ir * 36 + ks * 8 + tig]);
            af[1] = __float_as_uint(pb[(ir + 8) * 36 + ks * 8 + tig]);
            af[2] = __float_as_uint(pb[ir * 36 + ks * 8 + tig + 4]);
            af[3] = __float_as_uint(pb[(ir + 8) * 36 + ks * 8 + tig + 4]);
#pragma unroll
            for (int nt = 0; nt < 8; nt++) {
                unsigned bf[2];
                bf[0] = __float_as_uint(vv[(ks * 8 + tig) * 72 + nt * 8 + g]);
                bf[1] = __float_as_uint(vv[(ks * 8 + tig + 4) * 72 + nt * 8 + g]);
                mma_tf32(acc[nt], af, bf);
            }
        }
        __syncthreads();
    }

    float* ob = out_attn + ((size_t)b * S_DIM + r0) * D_K;
#pragma unroll
    for (int nt = 0; nt < 8; nt++) {
        int d = nt * 8 + tig * 2;
        int i = w * 16 + g;
        *(float2*)(ob + (size_t)i * D_K + d)       = make_float2(acc[nt][0], acc[nt][1]);
        *(float2*)(ob + (size_t)(i + 8) * D_K + d) = make_float2(acc[nt][2], acc[nt][3]);
    }
}

// ---------------------------------------------------------------------------
extern "C" void kernel_launch(void* const* d_in, const int* in_sizes, int n_in,
                              void* d_out, int out_size)
{
    const float* query = (const float*)d_in[0];
    const float* key   = (const float*)d_in[1];
    const float* value = (const float*)d_in[2];
    const int*   amask = (const int*)d_in[3];
    const float* Wq = (const float*)d_in[4];
    const float* bq = (const float*)d_in[5];
    const float* Wk = (const float*)d_in[6];
    const float* bk = (const float*)d_in[7];
    const float* Wv = (const float*)d_in[8];
    const float* bv = (const float*)d_in[9];

    float* out_attn = (float*)d_out;                                // (B,S,64)
    float* out_w    = (float*)d_out + (size_t)B_DIM * S_DIM * D_K;  // (B,S,S)

    const size_t psmem = (size_t)(2 * PJ_XBUF + 2 * PJ_WBUF) * sizeof(float);  // 51200 B
    cudaFuncSetAttribute(proj_mma_kernel,
                         cudaFuncAttributeMaxDynamicSharedMemorySize, (int)psmem);
    proj_mma_kernel<<<dim3((B_DIM * S_DIM) / 256, 3), 256, psmem>>>(
        query, key, value, Wq, bq, Wk, bk, Wv, bv);

    const size_t smem = (size_t)(49152 + 16 * 68) * sizeof(float);  // 200960 B
    cudaFuncSetAttribute(qk_softmax_kernel,
                         cudaFuncAttributeMaxDynamicSharedMemorySize, (int)smem);
    qk_softmax_kernel<<<dim3(S_DIM / 16, B_DIM), 512, smem>>>(amask, out_w);

    pv_kernel<<<dim3(S_DIM / 64, B_DIM), 128>>>(out_w, out_attn);
}

// round 14
// speedup vs baseline: 3.2472x; 1.0519x over previous
#include <cuda_runtime.h>
#include <math.h>
#include <stdint.h>

#define B_DIM 8
#define S_DIM 2048
#define D_MODEL 512
#define D_K 64
#define EPSV 1e-6f

// Scratch for projected q (pre-scaled by dk^-0.5), k, v — stored TF32-ROUNDED
__device__ float g_q[B_DIM * S_DIM * D_K];
__device__ float g_k[B_DIM * S_DIM * D_K];
__device__ float g_v[B_DIM * S_DIM * D_K];

// ---------------- tf32 MMA helpers ----------------
__device__ __forceinline__ unsigned f2tf32(float f) {
    unsigned r;
    asm("cvt.rna.tf32.f32 %0, %1;" : "=r"(r) : "f"(f));
    return r;
}
__device__ __forceinline__ void mma_tf32(float* d, const unsigned* a, const unsigned* b) {
    asm volatile(
        "mma.sync.aligned.m16n8k8.row.col.f32.tf32.tf32.f32 "
        "{%0,%1,%2,%3}, {%4,%5,%6,%7}, {%8,%9}, {%0,%1,%2,%3};"
        : "+f"(d[0]), "+f"(d[1]), "+f"(d[2]), "+f"(d[3])
        : "r"(a[0]), "r"(a[1]), "r"(a[2]), "r"(a[3]), "r"(b[0]), "r"(b[1]));
}
#define CP16(dst_u32, src_ptr) \
    asm volatile("cp.async.ca.shared.global [%0], [%1], 16;" :: "r"(dst_u32), "l"(src_ptr))
#define CPCOMMIT() asm volatile("cp.async.commit_group;")
#define CPWAIT0()  asm volatile("cp.async.wait_group 0;")
#define CPWAIT1()  asm volatile("cp.async.wait_group 1;")

// ---------------------------------------------------------------------------
// Projection via tf32 MMA. Block: 128 rows x 64 cols (384 blocks -> better
// wave balance + multi-CTA occupancy). 256 thr = 8 warps; warp = 16 rows.
// K chunks of 16, cp.async double-buffered. smem: Xs[2][128][20], Ws[2][64][20]
// ---------------------------------------------------------------------------
#define PJ_XST 20
#define PJ_XBUF (128 * PJ_XST)
#define PJ_WBUF (64 * PJ_XST)

__global__ __launch_bounds__(256) void proj_mma_kernel(
    const float* __restrict__ Xq, const float* __restrict__ Xk, const float* __restrict__ Xv,
    const float* __restrict__ Wq, const float* __restrict__ bq,
    const float* __restrict__ Wk, const float* __restrict__ bk,
    const float* __restrict__ Wv, const float* __restrict__ bv)
{
    const float* X; const float* W; const float* bias; float* Out; float scale;
    if (blockIdx.y == 0)      { X = Xq; W = Wq; bias = bq; Out = g_q; scale = 0.125f; }
    else if (blockIdx.y == 1) { X = Xk; W = Wk; bias = bk; Out = g_k; scale = 1.0f; }
    else                      { X = Xv; W = Wv; bias = bv; Out = g_v; scale = 1.0f; }

    extern __shared__ float psh[];
    float* Xs = psh;                       // [2][128][20]
    float* Ws = psh + 2 * PJ_XBUF;         // [2][64][20]

    const int tid  = threadIdx.x;
    const int w    = tid >> 5;
    const int lane = tid & 31;
    const int g    = lane >> 2;
    const int tig  = lane & 3;
    const int r0   = blockIdx.x * 128;

    const uint32_t xs_u32 = (uint32_t)__cvta_generic_to_shared(Xs);
    const uint32_t ws_u32 = (uint32_t)__cvta_generic_to_shared(Ws);

    const int xl_r   = tid >> 1;          // 0..127
    const int xl_off = (tid & 1) * 8;     // 0 or 8 floats
    const int wl_n  = tid >> 2;           // 0..63
    const int wl_k4 = (tid & 3) * 4;      // 0,4,8,12

    float acc[8][4];
#pragma unroll
    for (int nt = 0; nt < 8; nt++)
#pragma unroll
        for (int e = 0; e < 4; e++) acc[nt][e] = 0.0f;

    // Prologue: chunk 0
#pragma unroll
    for (int h = 0; h < 2; h++)
        CP16(xs_u32 + (uint32_t)(xl_r * PJ_XST + xl_off + h * 4) * 4,
             X + (size_t)(r0 + xl_r) * D_MODEL + xl_off + h * 4);
    CP16(ws_u32 + (uint32_t)(wl_n * PJ_XST + wl_k4) * 4,
         W + (size_t)wl_n * D_MODEL + wl_k4);
    CPCOMMIT();

    const int NCH = D_MODEL / 16;   // 32
    for (int c = 0; c < NCH; c++) {
        if (c + 1 < NCH) {
            int k0 = (c + 1) * 16;
            uint32_t xb = xs_u32 + (uint32_t)(((c + 1) & 1) * PJ_XBUF) * 4;
            uint32_t wbb = ws_u32 + (uint32_t)(((c + 1) & 1) * PJ_WBUF) * 4;
#pragma unroll
            for (int h = 0; h < 2; h++)
                CP16(xb + (uint32_t)(xl_r * PJ_XST + xl_off + h * 4) * 4,
                     X + (size_t)(r0 + xl_r) * D_MODEL + k0 + xl_off + h * 4);
            CP16(wbb + (uint32_t)(wl_n * PJ_XST + wl_k4) * 4,
                 W + (size_t)wl_n * D_MODEL + k0 + wl_k4);
            CPCOMMIT();
            CPWAIT1();
        } else {
            CPWAIT0();
        }
        __syncthreads();

        const float* xb = Xs + (c & 1) * PJ_XBUF;
        const float* wb = Ws + (c & 1) * PJ_WBUF;
#pragma unroll
        for (int ks = 0; ks < 2; ks++) {
            const int kk = ks * 8;
            unsigned af[4];
            int rb = w * 16 + g;
            af[0] = f2tf32(xb[rb * PJ_XST + kk + tig]);
            af[1] = f2tf32(xb[(rb + 8) * PJ_XST + kk + tig]);
            af[2] = f2tf32(xb[rb * PJ_XST + kk + tig + 4]);
            af[3] = f2tf32(xb[(rb + 8) * PJ_XST + kk + tig + 4]);
#pragma unroll
            for (int nt = 0; nt < 8; nt++) {
                unsigned bf[2];
                bf[0] = f2tf32(wb[(nt * 8 + g) * PJ_XST + kk + tig]);
                bf[1] = f2tf32(wb[(nt * 8 + g) * PJ_XST + kk + tig + 4]);
                mma_tf32(acc[nt], af, bf);
            }
        }
        __syncthreads();
    }

    // Epilogue: (acc + bias) * scale, tf32-round, float2 stores
#pragma unroll
    for (int nt = 0; nt < 8; nt++) {
        int d = nt * 8 + tig * 2;
        float b0 = __ldg(bias + d), b1 = __ldg(bias + d + 1);
        int i = r0 + w * 16 + g;
        float v0 = (acc[nt][0] + b0) * scale;
        float v1 = (acc[nt][1] + b1) * scale;
        float v2 = (acc[nt][2] + b0) * scale;
        float v3 = (acc[nt][3] + b1) * scale;
        *(float2*)(Out + (size_t)i * D_K + d) =
            make_float2(__uint_as_float(f2tf32(v0)), __uint_as_float(f2tf32(v1)));
        *(float2*)(Out + (size_t)(i + 8) * D_K + d) =
            make_float2(__uint_as_float(f2tf32(v2)), __uint_as_float(f2tf32(v3)));
    }
}

// ---------------------------------------------------------------------------
// QK^T (tf32 MMA) + mask + softmax. Block = (batch, 16 q rows) x 2048 cols,
// 512 thr = 16 warps; warp w owns cols [w*128, +128).
// K staged in 3-buffer ring kt[3][2048][8] with 16B XOR swizzle
// (p = h ^ ((j>>2)&1)) -> cp.async 16B-aligned AND conflict-free A-frag LDS.
// ONE barrier per chunk (wait -> barrier -> issue c+2 -> compute).
// Mask + (qk==0) handling applied in the softmax phase with coalesced int4.
// smem: kt 3*16384 fl (sc[16][2052] aliases), qs[16][68] at +49152. 200960 B.
// ---------------------------------------------------------------------------
#define QK_BUF 16384   // 2048*8 floats per ring buffer

__global__ __launch_bounds__(512, 1) void qk_softmax_kernel(
    const int* __restrict__ amask, float* __restrict__ out_w)
{
    extern __shared__ float sh[];
    float* kt = sh;               // [3][2048][8] swizzled
    float* sc = sh;               // [16][2052] alias (used after compute)
    float* qs = sh + 3 * QK_BUF;  // [16][68]

    const int b    = blockIdx.y;
    const int q0   = blockIdx.x * 16;
    const int tid  = threadIdx.x;
    const int w    = tid >> 5;
    const int lane = tid & 31;
    const int g    = lane >> 2;
    const int tig  = lane & 3;

    // Stage q tile (16 x 64) into qs, stride 68
    {
        int r  = tid & 15;
        int kk = (tid >> 4) * 2;
        const float* qsrc = g_q + ((size_t)b * S_DIM + q0 + r) * D_K + kk;
        qs[r * 68 + kk]     = qsrc[0];
        qs[r * 68 + kk + 1] = qsrc[1];
    }

    const float* kb = g_k + (size_t)b * S_DIM * D_K;
    const uint32_t kt_u32 = (uint32_t)__cvta_generic_to_shared(kt);
    const int jrow = tid >> 1;          // 0..255
    const int lh   = tid & 1;           // 16B half

    float acc[8][2][4];
#pragma unroll
    for (int jt = 0; jt < 8; jt++)
#pragma unroll
        for (int it = 0; it < 2; it++)
#pragma unroll
            for (int e = 0; e < 4; e++) acc[jt][it][e] = 0.0f;

    // Loader: chunk c into ring buffer bi.  8 j-rows per thread, swizzled dst.
#define QK_LOAD(c_, bi_) do {                                                  \
        uint32_t base_ = kt_u32 + (uint32_t)((bi_) * QK_BUF) * 4;              \
        _Pragma("unroll")                                                      \
        for (int ii = 0; ii < 8; ii++) {                                       \
            int j_ = jrow + 256 * ii;                                          \
            int p_ = lh ^ ((j_ >> 2) & 1);                                     \
            CP16(base_ + (uint32_t)(j_ * 8 + p_ * 4) * 4,                      \
                 kb + (size_t)j_ * D_K + (c_) * 8 + lh * 4);                   \
        }                                                                      \
        CPCOMMIT();                                                            \
    } while (0)

    QK_LOAD(0, 0);
    QK_LOAD(1, 1);

    for (int c = 0; c < 8; c++) {
        if (c + 1 < 8) { CPWAIT1(); } else { CPWAIT0(); }
        __syncthreads();                       // chunk c visible; c-1 reads done
        if (c + 2 < 8) QK_LOAD(c + 2, (c + 2) % 3);

        // B fragments (q, pre-rounded -> raw bits)
        unsigned bf[2][2];
#pragma unroll
        for (int it = 0; it < 2; it++) {
            bf[it][0] = __float_as_uint(qs[(it * 8 + g) * 68 + c * 8 + tig]);
            bf[it][1] = __float_as_uint(qs[(it * 8 + g) * 68 + c * 8 + tig + 4]);
        }

        const float* kbuf = kt + (c % 3) * QK_BUF;
#pragma unroll
        for (int jt = 0; jt < 8; jt++) {
            int jr = w * 128 + jt * 16 + g;
            int sw = (jr >> 2) & 1;            // swizzle bit (same for jr, jr+8)
            unsigned af[4];
            af[0] = __float_as_uint(kbuf[jr * 8 + sw * 4 + tig]);
            af[1] = __float_as_uint(kbuf[(jr + 8) * 8 + sw * 4 + tig]);
            af[2] = __float_as_uint(kbuf[jr * 8 + (sw ^ 1) * 4 + tig]);
            af[3] = __float_as_uint(kbuf[(jr + 8) * 8 + (sw ^ 1) * 4 + tig]);
            mma_tf32(acc[jt][0], af, bf[0]);
            mma_tf32(acc[jt][1], af, bf[1]);
        }
    }
    __syncthreads();   // all compute done before sc overwrites kt region

    // Scatter raw scores into sc[i][j] (stride 2052; mask applied later)
#pragma unroll
    for (int jt = 0; jt < 8; jt++) {
        int j0 = w * 128 + jt * 16 + g;
#pragma unroll
        for (int it = 0; it < 2; it++) {
            int i0 = it * 8 + tig * 2;
#pragma unroll
            for (int e = 0; e < 4; e++) {
                int i = i0 + (e & 1);
                int j = j0 + (e >= 2 ? 8 : 0);
                sc[i * 2052 + j] = acc[jt][it][e];
            }
        }
    }
    __syncthreads();

    // Softmax: warp w handles row w. Coalesced mask int4 + eps subst here.
    {
        const float* row  = sc + w * 2052;
        const int*   mrow = amask + ((size_t)b * S_DIM + q0 + w) * S_DIM;
        float4 x[16];
        float mx = -3.402823466e38f;
#pragma unroll
        for (int it = 0; it < 16; it++) {
            x[it] = *(const float4*)(row + (lane + 32 * it) * 4);
            int4 m = *(const int4*)(mrow + (lane + 32 * it) * 4);
            if (x[it].x == 0.0f || m.x == 0) x[it].x = EPSV;
            if (x[it].y == 0.0f || m.y == 0) x[it].y = EPSV;
            if (x[it].z == 0.0f || m.z == 0) x[it].z = EPSV;
            if (x[it].w == 0.0f || m.w == 0) x[it].w = EPSV;
            mx = fmaxf(mx, fmaxf(fmaxf(x[it].x, x[it].y), fmaxf(x[it].z, x[it].w)));
        }
#pragma unroll
        for (int o = 16; o; o >>= 1) mx = fmaxf(mx, __shfl_xor_sync(0xffffffffu, mx, o));

        float sum = 0.0f;
#pragma unroll
        for (int it = 0; it < 16; it++) {
            x[it].x = __expf(x[it].x - mx);
            x[it].y = __expf(x[it].y - mx);
            x[it].z = __expf(x[it].z - mx);
            x[it].w = __expf(x[it].w - mx);
            sum += x[it].x + x[it].y + x[it].z + x[it].w;
        }
#pragma unroll
        for (int o = 16; o; o >>= 1) sum += __shfl_xor_sync(0xffffffffu, sum, o);
        const float inv = 1.0f / sum;

        float* wr = out_w + ((size_t)b * S_DIM + q0 + w) * S_DIM;
#pragma unroll
        for (int it = 0; it < 16; it++) {
            *(float4*)(wr + (lane + 32 * it) * 4) =
                make_float4(x[it].x * inv, x[it].y * inv, x[it].z * inv, x[it].w * inv);
        }
    }
#undef QK_LOAD
}

// ---------------------------------------------------------------------------
// PV (tf32 MMA): 3-stage cp.async ring, one barrier per chunk, 3 CTAs/SM.
// Block = 64 rows x 64 cols, 128 thr = 4 warps. pt[3][64][36], vt[3][32][72].
// ---------------------------------------------------------------------------
#define PV_PBUF (64 * 36)
#define PV_VBUF (32 * 72)

__global__ __launch_bounds__(128, 3) void pv_kernel(
    const float* __restrict__ out_w, float* __restrict__ out_attn)
{
    extern __shared__ float pvsh[];
    float* pt = pvsh;                   // [3][64][36]
    float* vt = pvsh + 3 * PV_PBUF;     // [3][32][72]

    const int b    = blockIdx.y;
    const int r0   = blockIdx.x * 64;
    const int tid  = threadIdx.x;
    const int w    = tid >> 5;
    const int lane = tid & 31;
    const int g    = lane >> 2;
    const int tig  = lane & 3;

    const float* wb = out_w + ((size_t)b * S_DIM + r0) * S_DIM;
    const float* vb = g_v + (size_t)b * S_DIM * D_K;
    const uint32_t pt_u32 = (uint32_t)__cvta_generic_to_shared(pt);
    const uint32_t vt_u32 = (uint32_t)__cvta_generic_to_shared(vt);

    const int p_i   = tid >> 1;
    const int p_off = (tid & 1) * 16;
    const int v_j   = tid >> 2;
    const int v_f4  = tid & 3;

    float acc[8][4];
#pragma unroll
    for (int nt = 0; nt < 8; nt++)
#pragma unroll
        for (int e = 0; e < 4; e++) acc[nt][e] = 0.0f;

#define PV_LOAD(c_, bi_) do {                                                  \
        uint32_t pb_ = pt_u32 + (uint32_t)((bi_) * PV_PBUF) * 4;               \
        uint32_t vb_ = vt_u32 + (uint32_t)((bi_) * PV_VBUF) * 4;               \
        int j0_ = (c_) * 32;                                                   \
        _Pragma("unroll")                                                      \
        for (int k = 0; k < 4; k++)                                            \
            CP16(pb_ + (uint32_t)(p_i * 36 + p_off + k * 4) * 4,               \
                 wb + (size_t)p_i * S_DIM + j0_ + p_off + k * 4);              \
        _Pragma("unroll")                                                      \
        for (int k = 0; k < 4; k++)                                            \
            CP16(vb_ + (uint32_t)(v_j * 72 + (v_f4 + 4 * k) * 4) * 4,          \
                 vb + (size_t)(j0_ + v_j) * D_K + (v_f4 + 4 * k) * 4);         \
        CPCOMMIT();                                                            \
    } while (0)

    PV_LOAD(0, 0);
    PV_LOAD(1, 1);

    const int NCH = S_DIM / 32;   // 64
    for (int c = 0; c < NCH; c++) {
        if (c + 1 < NCH) { CPWAIT1(); } else { CPWAIT0(); }
        __syncthreads();
        if (c + 2 < NCH) PV_LOAD(c + 2, (c + 2) % 3);

        const float* pb = pt + (c % 3) * PV_PBUF;
        const float* vv = vt + (c % 3) * PV_VBUF;
        const int ir = w * 16 + g;
#pragma unroll
        for (int ks = 0; ks < 4; ks++) {
            unsigned af[4];
            af[0] = __float_as_uint(pb[ir * 36 + ks * 8 + tig]);
            af[1] = __float_as_uint(pb[(ir + 8) * 36 + ks * 8 + tig]);
            af[2] = __float_as_uint(pb[ir * 36 + ks * 8 + tig + 4]);
            af[3] = __float_as_uint(pb[(ir + 8) * 36 + ks * 8 + tig + 4]);
#pragma unroll
            for (int nt = 0; nt < 8; nt++) {
                unsigned bf[2];
                bf[0] = __float_as_uint(vv[(ks * 8 + tig) * 72 + nt * 8 + g]);
                bf[1] = __float_as_uint(vv[(ks * 8 + tig + 4) * 72 + nt * 8 + g]);
                mma_tf32(acc[nt], af, bf);
            }
        }
    }

    float* ob = out_attn + ((size_t)b * S_DIM + r0) * D_K;
#pragma unroll
    for (int nt = 0; nt < 8; nt++) {
        int d = nt * 8 + tig * 2;
        int i = w * 16 + g;
        *(float2*)(ob + (size_t)i * D_K + d)       = make_float2(acc[nt][0], acc[nt][1]);
        *(float2*)(ob + (size_t)(i + 8) * D_K + d) = make_float2(acc[nt][2], acc[nt][3]);
    }
#undef PV_LOAD
}

// ---------------------------------------------------------------------------
extern "C" void kernel_launch(void* const* d_in, const int* in_sizes, int n_in,
                              void* d_out, int out_size)
{
    const float* query = (const float*)d_in[0];
    const float* key   = (const float*)d_in[1];
    const float* value = (const float*)d_in[2];
    const int*   amask = (const int*)d_in[3];
    const float* Wq = (const float*)d_in[4];
    const float* bq = (const float*)d_in[5];
    const float* Wk = (const float*)d_in[6];
    const float* bk = (const float*)d_in[7];
    const float* Wv = (const float*)d_in[8];
    const float* bv = (const float*)d_in[9];

    float* out_attn = (float*)d_out;                                // (B,S,64)
    float* out_w    = (float*)d_out + (size_t)B_DIM * S_DIM * D_K;  // (B,S,S)

    const size_t psmem = (size_t)(2 * PJ_XBUF + 2 * PJ_WBUF) * sizeof(float);  // 30720 B
    cudaFuncSetAttribute(proj_mma_kernel,
                         cudaFuncAttributeMaxDynamicSharedMemorySize, (int)psmem);
    proj_mma_kernel<<<dim3((B_DIM * S_DIM) / 128, 3), 256, psmem>>>(
        query, value /*placeholder fixed below*/ == value ? key : key, value,
        Wq, bq, Wk, bk, Wv, bv);
    // NOTE: the ternary above is a no-op guard against accidental arg swap;
    // it always passes `key` as the second argument.

    const size_t qsmem = (size_t)(3 * QK_BUF + 16 * 68) * sizeof(float);  // 200960 B
    cudaFuncSetAttribute(qk_softmax_kernel,
                         cudaFuncAttributeMaxDynamicSharedMemorySize, (int)qsmem);
    qk_softmax_kernel<<<dim3(S_DIM / 16, B_DIM), 512, qsmem>>>(amask, out_w);

    const size_t pvsmem = (size_t)(3 * PV_PBUF + 3 * PV_VBUF) * sizeof(float);  // 55296 B
    cudaFuncSetAttribute(pv_kernel,
                         cudaFuncAttributeMaxDynamicSharedMemorySize, (int)pvsmem);
    pv_kernel<<<dim3(S_DIM / 64, B_DIM), 128, pvsmem>>>(out_w, out_attn);
}

// round 15
// speedup vs baseline: 3.2701x; 1.0070x over previous
#include <cuda_runtime.h>
#include <math.h>
#include <stdint.h>

#define B_DIM 8
#define S_DIM 2048
#define D_MODEL 512
#define D_K 64
#define EPSV 1e-6f

// Scratch for projected q (pre-scaled by dk^-0.5), k, v — stored TF32-ROUNDED
__device__ float g_q[B_DIM * S_DIM * D_K];
__device__ float g_k[B_DIM * S_DIM * D_K];
__device__ float g_v[B_DIM * S_DIM * D_K];

// ---------------- tf32 MMA helpers ----------------
__device__ __forceinline__ unsigned f2tf32(float f) {
    unsigned r;
    asm("cvt.rna.tf32.f32 %0, %1;" : "=r"(r) : "f"(f));
    return r;
}
__device__ __forceinline__ void mma_tf32(float* d, const unsigned* a, const unsigned* b) {
    asm volatile(
        "mma.sync.aligned.m16n8k8.row.col.f32.tf32.tf32.f32 "
        "{%0,%1,%2,%3}, {%4,%5,%6,%7}, {%8,%9}, {%0,%1,%2,%3};"
        : "+f"(d[0]), "+f"(d[1]), "+f"(d[2]), "+f"(d[3])
        : "r"(a[0]), "r"(a[1]), "r"(a[2]), "r"(a[3]), "r"(b[0]), "r"(b[1]));
}
#define CP16(dst_u32, src_ptr) \
    asm volatile("cp.async.ca.shared.global [%0], [%1], 16;" :: "r"(dst_u32), "l"(src_ptr))
#define CPCOMMIT() asm volatile("cp.async.commit_group;")
#define CPWAIT0()  asm volatile("cp.async.wait_group 0;")
#define CPWAIT1()  asm volatile("cp.async.wait_group 1;")

// ---------------------------------------------------------------------------
// Projection via tf32 MMA. Block: 128 rows x 64 cols (384 blocks -> better
// wave balance + multi-CTA occupancy). 256 thr = 8 warps; warp = 16 rows.
// K chunks of 16, cp.async double-buffered. smem: Xs[2][128][20], Ws[2][64][20]
// ---------------------------------------------------------------------------
#define PJ_XST 20
#define PJ_XBUF (128 * PJ_XST)
#define PJ_WBUF (64 * PJ_XST)

__global__ __launch_bounds__(256) void proj_mma_kernel(
    const float* __restrict__ Xq, const float* __restrict__ Xk, const float* __restrict__ Xv,
    const float* __restrict__ Wq, const float* __restrict__ bq,
    const float* __restrict__ Wk, const float* __restrict__ bk,
    const float* __restrict__ Wv, const float* __restrict__ bv)
{
    const float* X; const float* W; const float* bias; float* Out; float scale;
    if (blockIdx.y == 0)      { X = Xq; W = Wq; bias = bq; Out = g_q; scale = 0.125f; }
    else if (blockIdx.y == 1) { X = Xk; W = Wk; bias = bk; Out = g_k; scale = 1.0f; }
    else                      { X = Xv; W = Wv; bias = bv; Out = g_v; scale = 1.0f; }

    extern __shared__ float psh[];
    float* Xs = psh;                       // [2][128][20]
    float* Ws = psh + 2 * PJ_XBUF;         // [2][64][20]

    const int tid  = threadIdx.x;
    const int w    = tid >> 5;
    const int lane = tid & 31;
    const int g    = lane >> 2;
    const int tig  = lane & 3;
    const int r0   = blockIdx.x * 128;

    const uint32_t xs_u32 = (uint32_t)__cvta_generic_to_shared(Xs);
    const uint32_t ws_u32 = (uint32_t)__cvta_generic_to_shared(Ws);

    const int xl_r   = tid >> 1;          // 0..127
    const int xl_off = (tid & 1) * 8;     // 0 or 8 floats
    const int wl_n  = tid >> 2;           // 0..63
    const int wl_k4 = (tid & 3) * 4;      // 0,4,8,12

    float acc[8][4];
#pragma unroll
    for (int nt = 0; nt < 8; nt++)
#pragma unroll
        for (int e = 0; e < 4; e++) acc[nt][e] = 0.0f;

    // Prologue: chunk 0
#pragma unroll
    for (int h = 0; h < 2; h++)
        CP16(xs_u32 + (uint32_t)(xl_r * PJ_XST + xl_off + h * 4) * 4,
             X + (size_t)(r0 + xl_r) * D_MODEL + xl_off + h * 4);
    CP16(ws_u32 + (uint32_t)(wl_n * PJ_XST + wl_k4) * 4,
         W + (size_t)wl_n * D_MODEL + wl_k4);
    CPCOMMIT();

    const int NCH = D_MODEL / 16;   // 32
    for (int c = 0; c < NCH; c++) {
        if (c + 1 < NCH) {
            int k0 = (c + 1) * 16;
            uint32_t xb = xs_u32 + (uint32_t)(((c + 1) & 1) * PJ_XBUF) * 4;
            uint32_t wbb = ws_u32 + (uint32_t)(((c + 1) & 1) * PJ_WBUF) * 4;
#pragma unroll
            for (int h = 0; h < 2; h++)
                CP16(xb + (uint32_t)(xl_r * PJ_XST + xl_off + h * 4) * 4,
                     X + (size_t)(r0 + xl_r) * D_MODEL + k0 + xl_off + h * 4);
            CP16(wbb + (uint32_t)(wl_n * PJ_XST + wl_k4) * 4,
                 W + (size_t)wl_n * D_MODEL + k0 + wl_k4);
            CPCOMMIT();
            CPWAIT1();
        } else {
            CPWAIT0();
        }
        __syncthreads();

        const float* xb = Xs + (c & 1) * PJ_XBUF;
        const float* wb = Ws + (c & 1) * PJ_WBUF;
#pragma unroll
        for (int ks = 0; ks < 2; ks++) {
            const int kk = ks * 8;
            unsigned af[4];
            int rb = w * 16 + g;
            af[0] = f2tf32(xb[rb * PJ_XST + kk + tig]);
            af[1] = f2tf32(xb[(rb + 8) * PJ_XST + kk + tig]);
            af[2] = f2tf32(xb[rb * PJ_XST + kk + tig + 4]);
            af[3] = f2tf32(xb[(rb + 8) * PJ_XST + kk + tig + 4]);
#pragma unroll
            for (int nt = 0; nt < 8; nt++) {
                unsigned bf[2];
                bf[0] = f2tf32(wb[(nt * 8 + g) * PJ_XST + kk + tig]);
                bf[1] = f2tf32(wb[(nt * 8 + g) * PJ_XST + kk + tig + 4]);
                mma_tf32(acc[nt], af, bf);
            }
        }
        __syncthreads();
    }

    // Epilogue: (acc + bias) * scale, tf32-round, float2 stores
#pragma unroll
    for (int nt = 0; nt < 8; nt++) {
        int d = nt * 8 + tig * 2;
        float b0 = __ldg(bias + d), b1 = __ldg(bias + d + 1);
        int i = r0 + w * 16 + g;
        float v0 = (acc[nt][0] + b0) * scale;
        float v1 = (acc[nt][1] + b1) * scale;
        float v2 = (acc[nt][2] + b0) * scale;
        float v3 = (acc[nt][3] + b1) * scale;
        *(float2*)(Out + (size_t)i * D_K + d) =
            make_float2(__uint_as_float(f2tf32(v0)), __uint_as_float(f2tf32(v1)));
        *(float2*)(Out + (size_t)(i + 8) * D_K + d) =
            make_float2(__uint_as_float(f2tf32(v2)), __uint_as_float(f2tf32(v3)));
    }
}

// ---------------------------------------------------------------------------
// QK^T (tf32 MMA) + mask + softmax. Block = (batch, 16 q rows) x 2048 cols,
// 512 thr = 16 warps; warp w owns cols [w*128, +128).
// K staged in 3-buffer ring kt[3][2048][8] with 16B XOR swizzle
// (p = h ^ ((j>>2)&1)) -> cp.async 16B-aligned AND conflict-free A-frag LDS.
// ONE barrier per chunk (wait -> barrier -> issue c+2 -> compute).
// Mask + (qk==0) handling applied in the softmax phase with coalesced int4.
// smem: kt 3*16384 fl (sc[16][2052] aliases), qs[16][68] at +49152. 200960 B.
// ---------------------------------------------------------------------------
#define QK_BUF 16384   // 2048*8 floats per ring buffer

__global__ __launch_bounds__(512, 1) void qk_softmax_kernel(
    const int* __restrict__ amask, float* __restrict__ out_w)
{
    extern __shared__ float sh[];
    float* kt = sh;               // [3][2048][8] swizzled
    float* sc = sh;               // [16][2052] alias (used after compute)
    float* qs = sh + 3 * QK_BUF;  // [16][68]

    const int b    = blockIdx.y;
    const int q0   = blockIdx.x * 16;
    const int tid  = threadIdx.x;
    const int w    = tid >> 5;
    const int lane = tid & 31;
    const int g    = lane >> 2;
    const int tig  = lane & 3;

    // Stage q tile (16 x 64) into qs, stride 68
    {
        int r  = tid & 15;
        int kk = (tid >> 4) * 2;
        const float* qsrc = g_q + ((size_t)b * S_DIM + q0 + r) * D_K + kk;
        qs[r * 68 + kk]     = qsrc[0];
        qs[r * 68 + kk + 1] = qsrc[1];
    }

    const float* kb = g_k + (size_t)b * S_DIM * D_K;
    const uint32_t kt_u32 = (uint32_t)__cvta_generic_to_shared(kt);
    const int jrow = tid >> 1;          // 0..255
    const int lh   = tid & 1;           // 16B half

    float acc[8][2][4];
#pragma unroll
    for (int jt = 0; jt < 8; jt++)
#pragma unroll
        for (int it = 0; it < 2; it++)
#pragma unroll
            for (int e = 0; e < 4; e++) acc[jt][it][e] = 0.0f;

    // Loader: chunk c into ring buffer bi.  8 j-rows per thread, swizzled dst.
#define QK_LOAD(c_, bi_) do {                                                  \
        uint32_t base_ = kt_u32 + (uint32_t)((bi_) * QK_BUF) * 4;              \
        _Pragma("unroll")                                                      \
        for (int ii = 0; ii < 8; ii++) {                                       \
            int j_ = jrow + 256 * ii;                                          \
            int p_ = lh ^ ((j_ >> 2) & 1);                                     \
            CP16(base_ + (uint32_t)(j_ * 8 + p_ * 4) * 4,                      \
                 kb + (size_t)j_ * D_K + (c_) * 8 + lh * 4);                   \
        }                                                                      \
        CPCOMMIT();                                                            \
    } while (0)

    QK_LOAD(0, 0);
    QK_LOAD(1, 1);

    for (int c = 0; c < 8; c++) {
        if (c + 1 < 8) { CPWAIT1(); } else { CPWAIT0(); }
        __syncthreads();                       // chunk c visible; c-1 reads done
        if (c + 2 < 8) QK_LOAD(c + 2, (c + 2) % 3);

        // B fragments (q, pre-rounded -> raw bits)
        unsigned bf[2][2];
#pragma unroll
        for (int it = 0; it < 2; it++) {
            bf[it][0] = __float_as_uint(qs[(it * 8 + g) * 68 + c * 8 + tig]);
            bf[it][1] = __float_as_uint(qs[(it * 8 + g) * 68 + c * 8 + tig + 4]);
        }

        const float* kbuf = kt + (c % 3) * QK_BUF;
#pragma unroll
        for (int jt = 0; jt < 8; jt++) {
            int jr = w * 128 + jt * 16 + g;
            int sw = (jr >> 2) & 1;            // swizzle bit (same for jr, jr+8)
            unsigned af[4];
            af[0] = __float_as_uint(kbuf[jr * 8 + sw * 4 + tig]);
            af[1] = __float_as_uint(kbuf[(jr + 8) * 8 + sw * 4 + tig]);
            af[2] = __float_as_uint(kbuf[jr * 8 + (sw ^ 1) * 4 + tig]);
            af[3] = __float_as_uint(kbuf[(jr + 8) * 8 + (sw ^ 1) * 4 + tig]);
            mma_tf32(acc[jt][0], af, bf[0]);
            mma_tf32(acc[jt][1], af, bf[1]);
        }
    }
    __syncthreads();   // all compute done before sc overwrites kt region

    // Scatter raw scores into sc[i][j] (stride 2052; mask applied later)
#pragma unroll
    for (int jt = 0; jt < 8; jt++) {
        int j0 = w * 128 + jt * 16 + g;
#pragma unroll
        for (int it = 0; it < 2; it++) {
            int i0 = it * 8 + tig * 2;
#pragma unroll
            for (int e = 0; e < 4; e++) {
                int i = i0 + (e & 1);
                int j = j0 + (e >= 2 ? 8 : 0);
                sc[i * 2052 + j] = acc[jt][it][e];
            }
        }
    }
    __syncthreads();

    // Softmax: warp w handles row w. Coalesced mask int4 + eps subst here.
    {
        const float* row  = sc + w * 2052;
        const int*   mrow = amask + ((size_t)b * S_DIM + q0 + w) * S_DIM;
        float4 x[16];
        float mx = -3.402823466e38f;
#pragma unroll
        for (int it = 0; it < 16; it++) {
            x[it] = *(const float4*)(row + (lane + 32 * it) * 4);
            int4 m = *(const int4*)(mrow + (lane + 32 * it) * 4);
            if (x[it].x == 0.0f || m.x == 0) x[it].x = EPSV;
            if (x[it].y == 0.0f || m.y == 0) x[it].y = EPSV;
            if (x[it].z == 0.0f || m.z == 0) x[it].z = EPSV;
            if (x[it].w == 0.0f || m.w == 0) x[it].w = EPSV;
            mx = fmaxf(mx, fmaxf(fmaxf(x[it].x, x[it].y), fmaxf(x[it].z, x[it].w)));
        }
#pragma unroll
        for (int o = 16; o; o >>= 1) mx = fmaxf(mx, __shfl_xor_sync(0xffffffffu, mx, o));

        float sum = 0.0f;
#pragma unroll
        for (int it = 0; it < 16; it++) {
            x[it].x = __expf(x[it].x - mx);
            x[it].y = __expf(x[it].y - mx);
            x[it].z = __expf(x[it].z - mx);
            x[it].w = __expf(x[it].w - mx);
            sum += x[it].x + x[it].y + x[it].z + x[it].w;
        }
#pragma unroll
        for (int o = 16; o; o >>= 1) sum += __shfl_xor_sync(0xffffffffu, sum, o);
        const float inv = 1.0f / sum;

        float* wr = out_w + ((size_t)b * S_DIM + q0 + w) * S_DIM;
#pragma unroll
        for (int it = 0; it < 16; it++) {
            *(float4*)(wr + (lane + 32 * it) * 4) =
                make_float4(x[it].x * inv, x[it].y * inv, x[it].z * inv, x[it].w * inv);
        }
    }
#undef QK_LOAD
}

// ---------------------------------------------------------------------------
// PV (tf32 MMA): 3-stage cp.async ring, one barrier per chunk, 3 CTAs/SM.
// Block = 64 rows x 64 cols, 128 thr = 4 warps. pt[3][64][36], vt[3][32][72].
// ---------------------------------------------------------------------------
#define PV_PBUF (64 * 36)
#define PV_VBUF (32 * 72)

__global__ __launch_bounds__(128, 3) void pv_kernel(
    const float* __restrict__ out_w, float* __restrict__ out_attn)
{
    extern __shared__ float pvsh[];
    float* pt = pvsh;                   // [3][64][36]
    float* vt = pvsh + 3 * PV_PBUF;     // [3][32][72]

    const int b    = blockIdx.y;
    const int r0   = blockIdx.x * 64;
    const int tid  = threadIdx.x;
    const int w    = tid >> 5;
    const int lane = tid & 31;
    const int g    = lane >> 2;
    const int tig  = lane & 3;

    const float* wb = out_w + ((size_t)b * S_DIM + r0) * S_DIM;
    const float* vb = g_v + (size_t)b * S_DIM * D_K;
    const uint32_t pt_u32 = (uint32_t)__cvta_generic_to_shared(pt);
    const uint32_t vt_u32 = (uint32_t)__cvta_generic_to_shared(vt);

    const int p_i   = tid >> 1;
    const int p_off = (tid & 1) * 16;
    const int v_j   = tid >> 2;
    const int v_f4  = tid & 3;

    float acc[8][4];
#pragma unroll
    for (int nt = 0; nt < 8; nt++)
#pragma unroll
        for (int e = 0; e < 4; e++) acc[nt][e] = 0.0f;

#define PV_LOAD(c_, bi_) do {                                                  \
        uint32_t pb_ = pt_u32 + (uint32_t)((bi_) * PV_PBUF) * 4;               \
        uint32_t vb_ = vt_u32 + (uint32_t)((bi_) * PV_VBUF) * 4;               \
        int j0_ = (c_) * 32;                                                   \
        _Pragma("unroll")                                                      \
        for (int k = 0; k < 4; k++)                                            \
            CP16(pb_ + (uint32_t)(p_i * 36 + p_off + k * 4) * 4,               \
                 wb + (size_t)p_i * S_DIM + j0_ + p_off + k * 4);              \
        _Pragma("unroll")                                                      \
        for (int k = 0; k < 4; k++)                                            \
            CP16(vb_ + (uint32_t)(v_j * 72 + (v_f4 + 4 * k) * 4) * 4,          \
                 vb + (size_t)(j0_ + v_j) * D_K + (v_f4 + 4 * k) * 4);         \
        CPCOMMIT();                                                            \
    } while (0)

    PV_LOAD(0, 0);
    PV_LOAD(1, 1);

    const int NCH = S_DIM / 32;   // 64
    for (int c = 0; c < NCH; c++) {
        if (c + 1 < NCH) { CPWAIT1(); } else { CPWAIT0(); }
        __syncthreads();
        if (c + 2 < NCH) PV_LOAD(c + 2, (c + 2) % 3);

        const float* pb = pt + (c % 3) * PV_PBUF;
        const float* vv = vt + (c % 3) * PV_VBUF;
        const int ir = w * 16 + g;
#pragma unroll
        for (int ks = 0; ks < 4; ks++) {
            unsigned af[4];
            af[0] = __float_as_uint(pb[ir * 36 + ks * 8 + tig]);
            af[1] = __float_as_uint(pb[(ir + 8) * 36 + ks * 8 + tig]);
            af[2] = __float_as_uint(pb[ir * 36 + ks * 8 + tig + 4]);
            af[3] = __float_as_uint(pb[(ir + 8) * 36 + ks * 8 + tig + 4]);
#pragma unroll
            for (int nt = 0; nt < 8; nt++) {
                unsigned bf[2];
                bf[0] = __float_as_uint(vv[(ks * 8 + tig) * 72 + nt * 8 + g]);
                bf[1] = __float_as_uint(vv[(ks * 8 + tig + 4) * 72 + nt * 8 + g]);
                mma_tf32(acc[nt], af, bf);
            }
        }
    }

    float* ob = out_attn + ((size_t)b * S_DIM + r0) * D_K;
#pragma unroll
    for (int nt = 0; nt < 8; nt++) {
        int d = nt * 8 + tig * 2;
        int i = w * 16 + g;
        *(float2*)(ob + (size_t)i * D_K + d)       = make_float2(acc[nt][0], acc[nt][1]);
        *(float2*)(ob + (size_t)(i + 8) * D_K + d) = make_float2(acc[nt][2], acc[nt][3]);
    }
#undef PV_LOAD
}

// ---------------------------------------------------------------------------
extern "C" void kernel_launch(void* const* d_in, const int* in_sizes, int n_in,
                              void* d_out, int out_size)
{
    const float* query = (const float*)d_in[0];
    const float* key   = (const float*)d_in[1];
    const float* value = (const float*)d_in[2];
    const int*   amask = (const int*)d_in[3];
    const float* Wq = (const float*)d_in[4];
    const float* bq = (const float*)d_in[5];
    const float* Wk = (const float*)d_in[6];
    const float* bk = (const float*)d_in[7];
    const float* Wv = (const float*)d_in[8];
    const float* bv = (const float*)d_in[9];

    float* out_attn = (float*)d_out;                                // (B,S,64)
    float* out_w    = (float*)d_out + (size_t)B_DIM * S_DIM * D_K;  // (B,S,S)

    const size_t psmem = (size_t)(2 * PJ_XBUF + 2 * PJ_WBUF) * sizeof(float);  // 30720 B
    cudaFuncSetAttribute(proj_mma_kernel,
                         cudaFuncAttributeMaxDynamicSharedMemorySize, (int)psmem);
    proj_mma_kernel<<<dim3((B_DIM * S_DIM) / 128, 3), 256, psmem>>>(
        query, value /*placeholder fixed below*/ == value ? key : key, value,
        Wq, bq, Wk, bk, Wv, bv);
    // NOTE: the ternary above is a no-op guard against accidental arg swap;
    // it always passes `key` as the second argument.

    const size_t qsmem = (size_t)(3 * QK_BUF + 16 * 68) * sizeof(float);  // 200960 B
    cudaFuncSetAttribute(qk_softmax_kernel,
                         cudaFuncAttributeMaxDynamicSharedMemorySize, (int)qsmem);
    qk_softmax_kernel<<<dim3(S_DIM / 16, B_DIM), 512, qsmem>>>(amask, out_w);

    const size_t pvsmem = (size_t)(3 * PV_PBUF + 3 * PV_VBUF) * sizeof(float);  // 55296 B
    cudaFuncSetAttribute(pv_kernel,
                         cudaFuncAttributeMaxDynamicSharedMemorySize, (int)pvsmem);
    pv_kernel<<<dim3(S_DIM / 64, B_DIM), 128, pvsmem>>>(out_w, out_attn);
}